// round 4
// baseline (speedup 1.0000x reference)
#include <cuda_runtime.h>

typedef unsigned long long ull;

// ---------------- scratch (no allocations allowed) ----------------
// gh buffer: (B*S=128, 2*hid=256, H*W=1024) floats, reused by both layers
__device__ float g_gh[33554432];     // 128 MB
// layer-0 output: (B=4, S=32, hid=128, 1024)
__device__ float g_out0[16777216];   // 64 MB
// transposed weights [cin][k][cout], sized for layer 1 (128*9*256)
__device__ float g_wT[294912];

// ---------------- packed f32x2 helpers ----------------
__device__ __forceinline__ ull pack2(float lo, float hi) {
    ull d;
    asm("mov.b64 %0, {%1, %2};" : "=l"(d)
        : "r"(__float_as_uint(lo)), "r"(__float_as_uint(hi)));
    return d;
}
__device__ __forceinline__ void unpack2(ull v, float& lo, float& hi) {
    unsigned a, b;
    asm("mov.b64 {%0, %1}, %2;" : "=r"(a), "=r"(b) : "l"(v));
    lo = __uint_as_float(a);
    hi = __uint_as_float(b);
}
__device__ __forceinline__ ull ffma2(ull a, ull b, ull c) {
    ull d;
    asm("fma.rn.f32x2 %0, %1, %2, %3;" : "=l"(d) : "l"(a), "l"(b), "l"(c));
    return d;
}

// ---------------- weight transpose: w[co][ci][k] -> wT[(ci*9+k)*256+co] ----
template <int CIN>
__global__ void wtrans_kernel(const float* __restrict__ w) {
    int idx = blockIdx.x * 256 + threadIdx.x;   // grid sized exactly CIN*9
    int co = idx & 255;
    int rest = idx >> 8;
    int k = rest % 9;
    int ci = rest / 9;
    g_wT[idx] = w[(co * CIN + ci) * 9 + k];
}

// ---------------- fused 3x3 conv (implicit, direct) ----------------
// Block: 64 cout x (4 rows x 32 cols) of one image (bs). 256 threads:
//   tp = tid & 15  -> pixel pair (cols 2tp, 2tp+1) in each of the 4 rows
//   tc = tid >> 4  -> cout channels {tc + 16*j, j=0..3}
// Accumulate over cin in chunks of 4 via packed FFMA2 (2 pixels / instr).
template <int CIN, bool XG>
__global__ void __launch_bounds__(256, 2)
conv_kernel(const float* __restrict__ xin, const float* __restrict__ bias) {
    const int bx = blockIdx.x;   // row band 0..7  (h0 = 4*bx)
    const int cb = blockIdx.y;   // cout block 0..3 (64 couts)
    const int bs = blockIdx.z;   // 0..127 (b*32+s)
    const int tid = threadIdx.x;
    const int tp = tid & 15;
    const int tc = tid >> 4;
    const int h0 = bx * 4;

    __shared__ float xs[4][6][36];   // 4 cin x (rows h0-1..h0+4) x (cols -1..34)
    __shared__ float ws[4][9][64];   // 4 cin x 9 taps x 64 couts

    const float* x = XG ? (const float*)g_out0 : xin;
    const float* xbase = x + (size_t)bs * CIN * 1024;

    ull acc[4][4];
#pragma unroll
    for (int co = 0; co < 4; co++) {
        float bv = bias[cb * 64 + tc + 16 * co];
        ull bp = pack2(bv, bv);
#pragma unroll
        for (int orow = 0; orow < 4; orow++) acc[orow][co] = bp;
    }

#pragma unroll 1
    for (int cin0 = 0; cin0 < CIN; cin0 += 4) {
        // ---- fill xs (with zero halo) ----
        for (int idx = tid; idx < 4 * 6 * 36; idx += 256) {
            int ci = idx / 216;
            int rem = idx - ci * 216;
            int row = rem / 36;
            int cc = rem - row * 36;
            int xr = h0 - 1 + row;
            int xc = cc - 1;
            float v = 0.0f;
            if (xr >= 0 && xr < 32 && xc >= 0 && xc < 32)
                v = xbase[((cin0 + ci) * 32 + xr) * 32 + xc];
            xs[ci][row][cc] = v;
        }
        // ---- fill ws from transposed weights (coalesced over cout) ----
        for (int idx = tid; idx < 4 * 9 * 64; idx += 256) {
            int ci = idx / 576;
            int rem = idx - ci * 576;
            int k = rem / 64;
            int co = rem - k * 64;
            ws[ci][k][co] = g_wT[((cin0 + ci) * 9 + k) * 256 + cb * 64 + co];
        }
        __syncthreads();

#pragma unroll 1
        for (int ci = 0; ci < 4; ci++) {
#pragma unroll
            for (int r = 0; r < 3; r++) {
                ull wp[3][4];
#pragma unroll
                for (int c = 0; c < 3; c++) {
#pragma unroll
                    for (int co = 0; co < 4; co++) {
                        float wv = ws[ci][r * 3 + c][tc + 16 * co];
                        wp[c][co] = pack2(wv, wv);
                    }
                }
#pragma unroll
                for (int orow = 0; orow < 4; orow++) {
                    const float* xr = xs[ci][orow + r];
                    float2 va = *reinterpret_cast<const float2*>(xr + 2 * tp);
                    float2 vb = *reinterpret_cast<const float2*>(xr + 2 * tp + 2);
                    ull p0 = pack2(va.x, va.y);
                    ull p1 = pack2(va.y, vb.x);
                    ull p2 = pack2(vb.x, vb.y);
#pragma unroll
                    for (int co = 0; co < 4; co++)
                        acc[orow][co] = ffma2(p0, wp[0][co], acc[orow][co]);
#pragma unroll
                    for (int co = 0; co < 4; co++)
                        acc[orow][co] = ffma2(p1, wp[1][co], acc[orow][co]);
#pragma unroll
                    for (int co = 0; co < 4; co++)
                        acc[orow][co] = ffma2(p2, wp[2][co], acc[orow][co]);
                }
            }
        }
        __syncthreads();
    }

    // ---- store gh tile ----
    float* obase = g_gh + ((size_t)bs * 256 + cb * 64) * 1024 + h0 * 32;
#pragma unroll
    for (int co = 0; co < 4; co++) {
#pragma unroll
        for (int orow = 0; orow < 4; orow++) {
            float lo, hi;
            unpack2(acc[orow][co], lo, hi);
            float2 v = make_float2(lo, hi);
            *reinterpret_cast<float2*>(
                &obase[(tc + 16 * co) * 1024 + orow * 32 + 2 * tp]) = v;
        }
    }
}

// ---------------- minGRU sequential scan over S=32 ----------------
// h_t = (1 - z_t) h_{t-1} + z_t g(hidden_t), h0 = 0.5
// z = sigmoid(gate);  g(x) = x + 0.5 (x>=0) else sigmoid(x)
// LAYER 0 writes g_out0 + final slot 0; LAYER 1 writes dout + final slot 1.
template <int LAYER>
__global__ void scan_kernel(float* __restrict__ dout) {
    int u = blockIdx.x * 256 + threadIdx.x;   // (b, c, p): 4*128*1024 threads
    int p = u & 1023;
    int c = (u >> 10) & 127;
    int b = u >> 17;

    const float* gptr = g_gh + ((size_t)(b * 32) * 256 + c) * 1024 + p;
    float* optr = (LAYER == 0 ? g_out0 : dout) +
                  ((size_t)(b * 32) * 128 + c) * 1024 + p;

    float h = 0.5f;
#pragma unroll 4
    for (int s = 0; s < 32; s++) {
        float gate = gptr[0];
        float hd = gptr[131072];       // +128*1024: hidden half of gh
        gptr += 262144;                // next s
        float z = 1.0f / (1.0f + __expf(-gate));
        float g = (hd >= 0.0f) ? (hd + 0.5f) : 1.0f / (1.0f + __expf(-hd));
        h += z * (g - h);
        *optr = h;
        optr += 131072;                // next s in out
    }
    // stacked finals: (2, B, 1, hid, H, W) after the main output
    dout[16777216 + LAYER * 524288 + u] = h;
}

// ---------------- launch ----------------
extern "C" void kernel_launch(void* const* d_in, const int* in_sizes, int n_in,
                              void* d_out, int out_size) {
    const float* x  = (const float*)d_in[0];
    const float* w0 = (const float*)d_in[1];
    const float* b0 = (const float*)d_in[2];
    const float* w1 = (const float*)d_in[3];
    const float* b1 = (const float*)d_in[4];
    float* out = (float*)d_out;

    // layer 0
    wtrans_kernel<64><<<64 * 9, 256>>>(w0);
    conv_kernel<64, false><<<dim3(8, 4, 128), 256>>>(x, b0);
    scan_kernel<0><<<2048, 256>>>(out);
    // layer 1 (input = g_out0)
    wtrans_kernel<128><<<128 * 9, 256>>>(w1);
    conv_kernel<128, true><<<dim3(8, 4, 128), 256>>>(nullptr, b1);
    scan_kernel<1><<<2048, 256>>>(out);
}

// round 6
// speedup vs baseline: 2.6503x; 2.6503x over previous
#include <cuda_runtime.h>
#include <cuda_bf16.h>
#include <cstdint>

// ---------------- scratch (no allocations allowed) ----------------
// gh buffer: layout [bs=128][co=256][px=1024] fp32
__device__ float g_gh[33554432];     // 128 MB
// layer-0 output: [bs=128][c=128][px=1024]
__device__ float g_out0[16777216];   // 64 MB
// prepped bf16 weight chunks: 27 chunks x [256 co][64 k], hi and lo
__device__ __align__(16) __nv_bfloat16 g_Bh[442368];
__device__ __align__(16) __nv_bfloat16 g_Bl[442368];

// ---------------- warp MMA helpers (baseline sm_80+ instructions) ----------
__device__ __forceinline__ uint32_t smem_u32(const void* p) {
    uint32_t a;
    asm("{ .reg .u64 t; cvta.to.shared.u64 t, %1; cvt.u32.u64 %0, t; }"
        : "=r"(a) : "l"(p));
    return a;
}
__device__ __forceinline__ void ldmx4(uint32_t* r, uint32_t a) {
    asm volatile("ldmatrix.sync.aligned.m8n8.x4.shared.b16 {%0,%1,%2,%3}, [%4];"
                 : "=r"(r[0]), "=r"(r[1]), "=r"(r[2]), "=r"(r[3]) : "r"(a));
}
__device__ __forceinline__ void mma16816(float* c, const uint32_t* a,
                                         uint32_t b0, uint32_t b1) {
    asm volatile(
        "mma.sync.aligned.m16n8k16.row.col.f32.bf16.bf16.f32 "
        "{%0,%1,%2,%3}, {%4,%5,%6,%7}, {%8,%9}, {%0,%1,%2,%3};"
        : "+f"(c[0]), "+f"(c[1]), "+f"(c[2]), "+f"(c[3])
        : "r"(a[0]), "r"(a[1]), "r"(a[2]), "r"(a[3]), "r"(b0), "r"(b1));
}

// ---------------- weight prep: bf16 hi/lo chunks [g][co][kk] ---------------
// g<9: layer0 (CIN=64), tap=g, ci=kk. g>=9: layer1, l=g-9, cihalf=l/9,
// tap=l%9, ci=cihalf*64+kk.
__global__ void prep_kernel(const float* __restrict__ w0,
                            const float* __restrict__ w1) {
    int e = blockIdx.x * 256 + threadIdx.x;   // grid = 1728 -> 442368 exact
    int g = e >> 14;
    int rem = e & 16383;
    int co = rem >> 6;
    int kk = rem & 63;
    const float* w;
    int CIN, tap, ci;
    if (g < 9) { w = w0; CIN = 64; tap = g; ci = kk; }
    else { int l = g - 9; w = w1; CIN = 128; tap = l % 9; ci = (l / 9) * 64 + kk; }
    float v = w[(co * CIN + ci) * 9 + tap];
    __nv_bfloat16 hi = __float2bfloat16(v);
    __nv_bfloat16 lo = __float2bfloat16(v - __bfloat162float(hi));
    g_Bh[e] = hi;
    g_Bl[e] = lo;
}

// ---------------- smem layout (bytes) ----------------
constexpr int SM_BIAS = 0;          // 256 floats
constexpr int SM_RAW  = 1024;       // 64 ci x 205 floats = 52480
constexpr int SM_AH   = 53504;      // 128 rows x 144 B = 18432
constexpr int SM_AL   = 71936;      // 18432
constexpr int SM_BH   = 90368;      // 256 rows x 144 B = 36864
constexpr int SM_BL   = 127232;     // 36864
constexpr int SMEM_BYTES = 164096;
constexpr int SM_EPI  = 1024;       // epilogue union: 256 x 132 floats = 135168

// ---------------- conv via warp-level bf16 MMA (3-pass split) --------------
// CTA = (4-row px tile, image bs). 256 threads / 8 warps.
// D[128 px][256 cout], K chunks of 64 per tap. Warp tile m32 x n128.
template <int CIN, bool XG>
__global__ void __launch_bounds__(256)
conv_mma_kernel(const float* __restrict__ xin, const float* __restrict__ bias) {
    extern __shared__ char smem[];
    const uint32_t sb = smem_u32(smem);
    const int tid = threadIdx.x;
    const int wid = tid >> 5;
    const int lane = tid & 31;
    const int h0 = blockIdx.x * 4;   // 4 image rows
    const int bs = blockIdx.y;       // 0..127

    float* s_bias = (float*)(smem + SM_BIAS);
    float* raw = (float*)(smem + SM_RAW);
    s_bias[tid] = bias[tid];

    // warp tiling: 4 (m) x 2 (n)
    const int m0 = (wid & 3) * 32;
    const int n0 = (wid >> 2) * 128;
    // ldmatrix lane geometry
    const int mrowA = (lane & 7) + ((lane >> 3) & 1) * 8;
    const int kcolA = (lane >> 4) * 8;
    const int noffB = (lane & 7) + (lane >> 4) * 8;
    const int koffB = ((lane >> 3) & 1) * 8;
    const uint32_t aoff = (uint32_t)((m0 + mrowA) * 144 + kcolA * 2);
    const uint32_t boff = (uint32_t)((n0 + noffB) * 144 + koffB * 2);

    float acc[2][16][4];
#pragma unroll
    for (int m = 0; m < 2; m++)
#pragma unroll
        for (int nb = 0; nb < 16; nb++)
#pragma unroll
            for (int j = 0; j < 4; j++) acc[m][nb][j] = 0.0f;

#pragma unroll 1
    for (int cih = 0; cih < CIN / 64; cih++) {
        // ---- stage raw input half: 64 ci x 6 rows (h0-1..h0+4) x 34 cols ----
        const float* xb = (XG ? (const float*)g_out0 : xin) +
                          ((size_t)bs * CIN + cih * 64) * 1024;
        for (int i = tid; i < 64 * 204; i += 256) {
            int ci = i / 204;
            int rr = i - ci * 204;
            int y = rr / 34;
            int xc = rr - y * 34;
            int yy = h0 - 1 + y;
            int xx = xc - 1;
            float v = 0.0f;
            if (yy >= 0 && yy < 32 && xx >= 0 && xx < 32)
                v = xb[ci * 1024 + yy * 32 + xx];
            raw[ci * 205 + y * 34 + xc] = v;
        }
        __syncthreads();

#pragma unroll 1
        for (int tap = 0; tap < 9; tap++) {
            const int g = (CIN == 64) ? tap : (9 + cih * 9 + tap);
            const int ty = tap / 3, tx = tap % 3;

            // ---- build im2col A (hi/lo): lane = ci pair, 16 px per thread --
            {
                const float* rp0 = raw + (lane * 2) * 205 + ty * 34 + tx;
#pragma unroll
                for (int i = 0; i < 16; i++) {
                    int px = wid * 16 + i;
                    int r = px >> 5, c = px & 31;
                    const float* rp = rp0 + r * 34 + c;
                    float v0 = rp[0];
                    float v1 = rp[205];
                    __nv_bfloat162 hh, ll;
                    hh.x = __float2bfloat16(v0);
                    hh.y = __float2bfloat16(v1);
                    ll.x = __float2bfloat16(v0 - __bfloat162float(hh.x));
                    ll.y = __float2bfloat16(v1 - __bfloat162float(hh.y));
                    uint32_t o = (uint32_t)(px * 144 + lane * 4);
                    *(__nv_bfloat162*)(smem + SM_AH + o) = hh;
                    *(__nv_bfloat162*)(smem + SM_AL + o) = ll;
                }
            }
            // ---- copy B chunk [256 co][64 k] hi/lo into 144B-padded rows ---
            {
                const uint4* sh = (const uint4*)(g_Bh + g * 16384);
                const uint4* sl = (const uint4*)(g_Bl + g * 16384);
                for (int i = tid; i < 2048; i += 256) {
                    int row = i >> 3, c8 = i & 7;
                    uint32_t o = (uint32_t)(row * 144 + c8 * 16);
                    *(uint4*)(smem + SM_BH + o) = sh[i];
                    *(uint4*)(smem + SM_BL + o) = sl[i];
                }
            }
            __syncthreads();

            // ---- 3 passes x 4 k-steps x 32 mma ----
#pragma unroll
            for (int pass = 0; pass < 3; pass++) {
                const uint32_t Ab = sb + (pass == 2 ? SM_AL : SM_AH) + aoff;
                const uint32_t Bb = sb + (pass == 1 ? SM_BL : SM_BH) + boff;
#pragma unroll
                for (int ks = 0; ks < 4; ks++) {
                    uint32_t Af[2][4];
                    ldmx4(Af[0], Ab + ks * 32);
                    ldmx4(Af[1], Ab + 16 * 144 + ks * 32);
#pragma unroll
                    for (int nh = 0; nh < 2; nh++) {
                        uint32_t Bf[4][4];
#pragma unroll
                        for (int p = 0; p < 4; p++)
                            ldmx4(Bf[p], Bb + (nh * 64 + p * 16) * 144 + ks * 32);
#pragma unroll
                        for (int p = 0; p < 4; p++) {
                            int nb = nh * 8 + p * 2;
                            mma16816(acc[0][nb],     Af[0], Bf[p][0], Bf[p][1]);
                            mma16816(acc[1][nb],     Af[1], Bf[p][0], Bf[p][1]);
                            mma16816(acc[0][nb + 1], Af[0], Bf[p][2], Bf[p][3]);
                            mma16816(acc[1][nb + 1], Af[1], Bf[p][2], Bf[p][3]);
                        }
                    }
                }
            }
            __syncthreads();   // A/B reused next tap
        }
    }

    // ---- epilogue: acc -> smem [co][px] (stride 132) -> coalesced gmem ----
    float* epi = (float*)(smem + SM_EPI);
#pragma unroll
    for (int m = 0; m < 2; m++) {
#pragma unroll
        for (int nb = 0; nb < 16; nb++) {
            int co = n0 + nb * 8 + 2 * (lane & 3);
            int px = m0 + m * 16 + (lane >> 2);
            epi[co * 132 + px] = acc[m][nb][0];
            epi[(co + 1) * 132 + px] = acc[m][nb][1];
            epi[co * 132 + px + 8] = acc[m][nb][2];
            epi[(co + 1) * 132 + px + 8] = acc[m][nb][3];
        }
    }
    __syncthreads();
    {
        float* ghb = g_gh + (size_t)bs * 256 * 1024 + h0 * 32;
        for (int i = tid; i < 8192; i += 256) {
            int co = i >> 5;
            int p4 = (i & 31) * 4;
            float4 v = *(float4*)(epi + co * 132 + p4);
            float bv = s_bias[co];
            v.x += bv; v.y += bv; v.z += bv; v.w += bv;
            *(float4*)(ghb + (size_t)co * 1024 + p4) = v;
        }
    }
}

// ---------------- minGRU sequential scan over S=32 (unchanged) -------------
template <int LAYER>
__global__ void scan_kernel(float* __restrict__ dout) {
    int u = blockIdx.x * 256 + threadIdx.x;   // (b, c, p)
    int p = u & 1023;
    int c = (u >> 10) & 127;
    int b = u >> 17;

    const float* gptr = g_gh + ((size_t)(b * 32) * 256 + c) * 1024 + p;
    float* optr = (LAYER == 0 ? g_out0 : dout) +
                  ((size_t)(b * 32) * 128 + c) * 1024 + p;

    float h = 0.5f;
#pragma unroll 4
    for (int s = 0; s < 32; s++) {
        float gate = gptr[0];
        float hd = gptr[131072];
        gptr += 262144;
        float z = 1.0f / (1.0f + __expf(-gate));
        float g = (hd >= 0.0f) ? (hd + 0.5f) : 1.0f / (1.0f + __expf(-hd));
        h += z * (g - h);
        *optr = h;
        optr += 131072;
    }
    dout[16777216 + LAYER * 524288 + u] = h;
}

// ---------------- launch ----------------
extern "C" void kernel_launch(void* const* d_in, const int* in_sizes, int n_in,
                              void* d_out, int out_size) {
    const float* x  = (const float*)d_in[0];
    const float* w0 = (const float*)d_in[1];
    const float* b0 = (const float*)d_in[2];
    const float* w1 = (const float*)d_in[3];
    const float* b1 = (const float*)d_in[4];
    float* out = (float*)d_out;

    cudaFuncSetAttribute(conv_mma_kernel<64, false>,
                         cudaFuncAttributeMaxDynamicSharedMemorySize, SMEM_BYTES);
    cudaFuncSetAttribute(conv_mma_kernel<128, true>,
                         cudaFuncAttributeMaxDynamicSharedMemorySize, SMEM_BYTES);

    prep_kernel<<<1728, 256>>>(w0, w1);
    conv_mma_kernel<64, false><<<dim3(8, 128), 256, SMEM_BYTES>>>(x, b0);
    scan_kernel<0><<<2048, 256>>>(out);
    conv_mma_kernel<128, true><<<dim3(8, 128), 256, SMEM_BYTES>>>(nullptr, b1);
    scan_kernel<1><<<2048, 256>>>(out);
}

// round 8
// speedup vs baseline: 3.6227x; 1.3669x over previous
#include <cuda_runtime.h>
#include <cuda_bf16.h>
#include <cstdint>

// ---------------- scratch (no allocations allowed) ----------------
// gh buffer: layout [bs=128][co=256][px=1024] fp32
__device__ float g_gh[33554432];     // 128 MB
// layer-0 output: [bs=128][c=128][px=1024]
__device__ float g_out0[16777216];   // 64 MB
// prepped bf16 weight chunks: 27 chunks x [256 co][64 k], hi and lo
__device__ __align__(16) __nv_bfloat16 g_Bh[442368];
__device__ __align__(16) __nv_bfloat16 g_Bl[442368];

// ---------------- warp MMA helpers (baseline sm_80+ instructions) ----------
__device__ __forceinline__ uint32_t smem_u32(const void* p) {
    uint32_t a;
    asm("{ .reg .u64 t; cvta.to.shared.u64 t, %1; cvt.u32.u64 %0, t; }"
        : "=r"(a) : "l"(p));
    return a;
}
__device__ __forceinline__ void ldmx4(uint32_t* r, uint32_t a) {
    asm volatile("ldmatrix.sync.aligned.m8n8.x4.shared.b16 {%0,%1,%2,%3}, [%4];"
                 : "=r"(r[0]), "=r"(r[1]), "=r"(r[2]), "=r"(r[3]) : "r"(a));
}
__device__ __forceinline__ void mma16816(float* c, const uint32_t* a,
                                         uint32_t b0, uint32_t b1) {
    asm volatile(
        "mma.sync.aligned.m16n8k16.row.col.f32.bf16.bf16.f32 "
        "{%0,%1,%2,%3}, {%4,%5,%6,%7}, {%8,%9}, {%0,%1,%2,%3};"
        : "+f"(c[0]), "+f"(c[1]), "+f"(c[2]), "+f"(c[3])
        : "r"(a[0]), "r"(a[1]), "r"(a[2]), "r"(a[3]), "r"(b0), "r"(b1));
}
__device__ __forceinline__ void cp16(uint32_t d, const void* s) {
    asm volatile("cp.async.cg.shared.global [%0], [%1], 16;" :: "r"(d), "l"(s));
}
#define CP_COMMIT() asm volatile("cp.async.commit_group;" ::: "memory")
#define CP_WAIT0()  asm volatile("cp.async.wait_group 0;" ::: "memory")

// ---------------- weight prep: bf16 hi/lo chunks [g][co][kk] ---------------
// g<9: layer0 (CIN=64), tap=g, ci=kk. g>=9: layer1, l=g-9, cihalf=l/9,
// tap=l%9, ci=cihalf*64+kk.
__global__ void prep_kernel(const float* __restrict__ w0,
                            const float* __restrict__ w1) {
    int e = blockIdx.x * 256 + threadIdx.x;   // grid = 1728 -> 442368 exact
    int g = e >> 14;
    int rem = e & 16383;
    int co = rem >> 6;
    int kk = rem & 63;
    const float* w;
    int CIN, tap, ci;
    if (g < 9) { w = w0; CIN = 64; tap = g; ci = kk; }
    else { int l = g - 9; w = w1; CIN = 128; tap = l % 9; ci = (l / 9) * 64 + kk; }
    float v = w[(co * CIN + ci) * 9 + tap];
    __nv_bfloat16 hi = __float2bfloat16(v);
    __nv_bfloat16 lo = __float2bfloat16(v - __bfloat162float(hi));
    g_Bh[e] = hi;
    g_Bl[e] = lo;
}

// ---------------- smem layout (bytes) ----------------
// raw bf16 input half, [y=6][x=34][ci=64] padded to 72 ci (144 B rows)
constexpr int SM_BIAS  = 0;                 // 128 floats (512 B)
constexpr int SM_RAWH  = 512;
constexpr int RAW_HALF = 29376;             // 6*34*72*2
constexpr int SM_RAWL  = SM_RAWH + RAW_HALF;       // 29888
constexpr int SM_BH    = 59264;             // 128 rows x 144 B = 18432
constexpr int B_HALF   = 18432;
constexpr int SM_BL    = SM_BH + B_HALF;           // 77696
constexpr int SMEM_BYTES = 96128;
constexpr int SM_EPI   = 512;               // reuse: 128 x 132 floats = 67584

// ---------------- conv via warp-level bf16 MMA (3-pass split) --------------
// CTA = (4-row px tile, co half, image bs). 256 threads / 8 warps.
// CTA tile: D[128 px][128 co]. Warp tile m32 x n64 (4m x 2n warps).
// A fragments come straight from the [y][x][ci] raw buffer: per-tap A is
// just a +((ty*34+tx)*144) address offset -- no per-tap rebuild.
template <int CIN, bool XG>
__global__ void __launch_bounds__(256, 2)
conv_mma_kernel(const float* __restrict__ xin, const float* __restrict__ bias) {
    extern __shared__ char smem[];
    const uint32_t sb = smem_u32(smem);
    const int tid = threadIdx.x;
    const int wid = tid >> 5;
    const int lane = tid & 31;
    const int h0 = blockIdx.x * 4;     // 4 image rows
    const int coh = blockIdx.y;        // co half 0..1
    const int bs = blockIdx.z;         // 0..127

    float* s_bias = (float*)(smem + SM_BIAS);
    if (tid < 128) s_bias[tid] = bias[coh * 128 + tid];

    // warp tiling: 4 (m) x 2 (n)
    const int m0 = (wid & 3) * 32;
    const int n0r = (wid >> 2) * 64;
    // ldmatrix lane geometry (same as validated R6 mapping)
    const int mrowA = (lane & 7) + ((lane >> 3) & 1) * 8;
    const int kcolA = (lane >> 4) * 8;
    const int noffB = (lane & 7) + (lane >> 4) * 8;
    const int koffB = ((lane >> 3) & 1) * 8;
    // A lane base addresses (tap 0, hi buffer) for the two m16 tiles
    const int px0 = m0 + mrowA, px1 = px0 + 16;
    const uint32_t aB0 = sb + SM_RAWH +
        (uint32_t)(((px0 >> 5) * 34 + (px0 & 31)) * 144 + kcolA * 2);
    const uint32_t aB1 = sb + SM_RAWH +
        (uint32_t)(((px1 >> 5) * 34 + (px1 & 31)) * 144 + kcolA * 2);
    const uint32_t bB = sb + SM_BH +
        (uint32_t)((n0r + noffB) * 144 + koffB * 2);

    float acc[2][8][4];
#pragma unroll
    for (int m = 0; m < 2; m++)
#pragma unroll
        for (int nb = 0; nb < 8; nb++)
#pragma unroll
            for (int j = 0; j < 4; j++) acc[m][nb][j] = 0.0f;

#pragma unroll 1
    for (int cih = 0; cih < CIN / 64; cih++) {
        __syncthreads();   // all prior MMAs done reading rawh/rawl
        // ---- stage + convert raw half: [y=6][x=34][ci=64] hi/lo bf16 ----
        const float* xb = (XG ? (const float*)g_out0 : xin) +
                          ((size_t)bs * CIN + cih * 64) * 1024;
        for (int i = tid; i < 64 * 204; i += 256) {
            int ci = i / 204;
            int rr = i - ci * 204;
            int y = rr / 34;
            int xc = rr - y * 34;
            int yy = h0 - 1 + y;
            int xx = xc - 1;
            float v = 0.0f;
            if (yy >= 0 && yy < 32 && xx >= 0 && xx < 32)
                v = xb[ci * 1024 + yy * 32 + xx];
            __nv_bfloat16 hi = __float2bfloat16(v);
            __nv_bfloat16 lo = __float2bfloat16(v - __bfloat162float(hi));
            int off = (y * 34 + xc) * 72 + ci;
            ((__nv_bfloat16*)(smem + SM_RAWH))[off] = hi;
            ((__nv_bfloat16*)(smem + SM_RAWL))[off] = lo;
        }

#pragma unroll 1
        for (int tap = 0; tap < 9; tap++) {
            const int g = (CIN == 64) ? tap : (9 + cih * 9 + tap);
            __syncthreads();   // prev-tap B reads done; staging visible
            // ---- B chunk [128 co][64 k] hi/lo via cp.async ----
            // 128 rows x 128 B = 1024 x 16-B chunks (8 chunks per row).
            {
                const uint4* sh = (const uint4*)(g_Bh + g * 16384 + coh * 8192);
                const uint4* sl = (const uint4*)(g_Bl + g * 16384 + coh * 8192);
#pragma unroll
                for (int i = tid; i < 1024; i += 256) {
                    int row = i >> 3, c8 = i & 7;
                    uint32_t d = sb + SM_BH + row * 144 + c8 * 16;
                    cp16(d, sh + i);
                    cp16(d + B_HALF, sl + i);
                }
            }
            CP_COMMIT();
            CP_WAIT0();
            __syncthreads();

            const uint32_t toff = (uint32_t)(((tap / 3) * 34 + (tap % 3)) * 144);
            const uint32_t a0 = aB0 + toff, a1 = aB1 + toff;

#pragma unroll
            for (int ks = 0; ks < 4; ks++) {
                const uint32_t kb = ks * 32;
                uint32_t Ah0[4], Ah1[4], Al0[4], Al1[4], Bf[4][4];
                ldmx4(Ah0, a0 + kb);
                ldmx4(Ah1, a1 + kb);
#pragma unroll
                for (int p = 0; p < 4; p++) ldmx4(Bf[p], bB + p * 2304 + kb);
                // pass Ah*Bh
#pragma unroll
                for (int p = 0; p < 4; p++) {
                    mma16816(acc[0][2 * p],     Ah0, Bf[p][0], Bf[p][1]);
                    mma16816(acc[1][2 * p],     Ah1, Bf[p][0], Bf[p][1]);
                    mma16816(acc[0][2 * p + 1], Ah0, Bf[p][2], Bf[p][3]);
                    mma16816(acc[1][2 * p + 1], Ah1, Bf[p][2], Bf[p][3]);
                }
                // pass Al*Bh
                ldmx4(Al0, a0 + RAW_HALF + kb);
                ldmx4(Al1, a1 + RAW_HALF + kb);
#pragma unroll
                for (int p = 0; p < 4; p++) {
                    mma16816(acc[0][2 * p],     Al0, Bf[p][0], Bf[p][1]);
                    mma16816(acc[1][2 * p],     Al1, Bf[p][0], Bf[p][1]);
                    mma16816(acc[0][2 * p + 1], Al0, Bf[p][2], Bf[p][3]);
                    mma16816(acc[1][2 * p + 1], Al1, Bf[p][2], Bf[p][3]);
                }
                // pass Ah*Bl
#pragma unroll
                for (int p = 0; p < 4; p++)
                    ldmx4(Bf[p], bB + B_HALF + p * 2304 + kb);
#pragma unroll
                for (int p = 0; p < 4; p++) {
                    mma16816(acc[0][2 * p],     Ah0, Bf[p][0], Bf[p][1]);
                    mma16816(acc[1][2 * p],     Ah1, Bf[p][0], Bf[p][1]);
                    mma16816(acc[0][2 * p + 1], Ah0, Bf[p][2], Bf[p][3]);
                    mma16816(acc[1][2 * p + 1], Ah1, Bf[p][2], Bf[p][3]);
                }
            }
        }
    }

    // ---- epilogue: acc -> smem [co][px] (stride 132) -> coalesced gmem ----
    __syncthreads();
    float* epi = (float*)(smem + SM_EPI);
#pragma unroll
    for (int m = 0; m < 2; m++) {
#pragma unroll
        for (int nb = 0; nb < 8; nb++) {
            int co = n0r + nb * 8 + 2 * (lane & 3);
            int px = m0 + m * 16 + (lane >> 2);
            epi[co * 132 + px] = acc[m][nb][0];
            epi[(co + 1) * 132 + px] = acc[m][nb][1];
            epi[co * 132 + px + 8] = acc[m][nb][2];
            epi[(co + 1) * 132 + px + 8] = acc[m][nb][3];
        }
    }
    __syncthreads();
    {
        float* ghb = g_gh + ((size_t)bs * 256 + coh * 128) * 1024 + h0 * 32;
        for (int i = tid; i < 4096; i += 256) {
            int co = i >> 5;
            int p4 = (i & 31) * 4;
            float4 v = *(float4*)(epi + co * 132 + p4);
            float bv = s_bias[co];
            v.x += bv; v.y += bv; v.z += bv; v.w += bv;
            *(float4*)(ghb + (size_t)co * 1024 + p4) = v;
        }
    }
}

// ---------------- minGRU sequential scan over S=32 -------------------------
template <int LAYER>
__global__ void scan_kernel(float* __restrict__ dout) {
    int u = blockIdx.x * 256 + threadIdx.x;   // (b, c, p)
    int p = u & 1023;
    int c = (u >> 10) & 127;
    int b = u >> 17;

    const float* gptr = g_gh + ((size_t)(b * 32) * 256 + c) * 1024 + p;
    float* optr = (LAYER == 0 ? g_out0 : dout) +
                  ((size_t)(b * 32) * 128 + c) * 1024 + p;

    float h = 0.5f;
#pragma unroll 4
    for (int s = 0; s < 32; s++) {
        float gate = gptr[0];
        float hd = gptr[131072];
        gptr += 262144;
        float z = 1.0f / (1.0f + __expf(-gate));
        float g = (hd >= 0.0f) ? (hd + 0.5f) : 1.0f / (1.0f + __expf(-hd));
        h += z * (g - h);
        *optr = h;
        optr += 131072;
    }
    dout[16777216 + LAYER * 524288 + u] = h;
}

// ---------------- launch ----------------
extern "C" void kernel_launch(void* const* d_in, const int* in_sizes, int n_in,
                              void* d_out, int out_size) {
    const float* x  = (const float*)d_in[0];
    const float* w0 = (const float*)d_in[1];
    const float* b0 = (const float*)d_in[2];
    const float* w1 = (const float*)d_in[3];
    const float* b1 = (const float*)d_in[4];
    float* out = (float*)d_out;

    cudaFuncSetAttribute(conv_mma_kernel<64, false>,
                         cudaFuncAttributeMaxDynamicSharedMemorySize, SMEM_BYTES);
    cudaFuncSetAttribute(conv_mma_kernel<128, true>,
                         cudaFuncAttributeMaxDynamicSharedMemorySize, SMEM_BYTES);

    prep_kernel<<<1728, 256>>>(w0, w1);
    conv_mma_kernel<64, false><<<dim3(8, 2, 128), 256, SMEM_BYTES>>>(x, b0);
    scan_kernel<0><<<2048, 256>>>(out);
    conv_mma_kernel<128, true><<<dim3(8, 2, 128), 256, SMEM_BYTES>>>(nullptr, b1);
    scan_kernel<1><<<2048, 256>>>(out);
}

// round 9
// speedup vs baseline: 3.7135x; 1.0251x over previous
#include <cuda_runtime.h>
#include <cuda_bf16.h>
#include <cstdint>

// ---------------- scratch (no allocations allowed) ----------------
// gh buffer: layout [bs=128][co=256][px=1024] fp32
__device__ float g_gh[33554432];     // 128 MB
// layer-0 output: [bs=128][c=128][px=1024]
__device__ float g_out0[16777216];   // 64 MB
// prepped bf16 weight chunks: 27 chunks x [256 co][64 k], hi and lo
__device__ __align__(16) __nv_bfloat16 g_Bh[442368];
__device__ __align__(16) __nv_bfloat16 g_Bl[442368];

// ---------------- warp MMA helpers (baseline sm_80+ instructions) ----------
__device__ __forceinline__ uint32_t smem_u32(const void* p) {
    uint32_t a;
    asm("{ .reg .u64 t; cvta.to.shared.u64 t, %1; cvt.u32.u64 %0, t; }"
        : "=r"(a) : "l"(p));
    return a;
}
__device__ __forceinline__ void ldmx4(uint32_t* r, uint32_t a) {
    asm volatile("ldmatrix.sync.aligned.m8n8.x4.shared.b16 {%0,%1,%2,%3}, [%4];"
                 : "=r"(r[0]), "=r"(r[1]), "=r"(r[2]), "=r"(r[3]) : "r"(a));
}
__device__ __forceinline__ void mma16816(float* c, const uint32_t* a,
                                         uint32_t b0, uint32_t b1) {
    asm volatile(
        "mma.sync.aligned.m16n8k16.row.col.f32.bf16.bf16.f32 "
        "{%0,%1,%2,%3}, {%4,%5,%6,%7}, {%8,%9}, {%0,%1,%2,%3};"
        : "+f"(c[0]), "+f"(c[1]), "+f"(c[2]), "+f"(c[3])
        : "r"(a[0]), "r"(a[1]), "r"(a[2]), "r"(a[3]), "r"(b0), "r"(b1));
}
__device__ __forceinline__ void cp16(uint32_t d, const void* s) {
    asm volatile("cp.async.cg.shared.global [%0], [%1], 16;" :: "r"(d), "l"(s));
}
#define CP_COMMIT() asm volatile("cp.async.commit_group;" ::: "memory")
#define CP_WAIT0()  asm volatile("cp.async.wait_group 0;" ::: "memory")
#define CP_WAIT1()  asm volatile("cp.async.wait_group 1;" ::: "memory")

// ---------------- weight prep: bf16 hi/lo chunks [g][co][kk] ---------------
// g<9: layer0 (CIN=64), tap=g, ci=kk. g>=9: layer1, l=g-9, cihalf=l/9,
// tap=l%9, ci=cihalf*64+kk.  Note: for CIN=128, g is consecutive over
// (cih, tap) in exactly the kernel's iteration order.
__global__ void prep_kernel(const float* __restrict__ w0,
                            const float* __restrict__ w1) {
    int e = blockIdx.x * 256 + threadIdx.x;   // grid = 1728 -> 442368 exact
    int g = e >> 14;
    int rem = e & 16383;
    int co = rem >> 6;
    int kk = rem & 63;
    const float* w;
    int CIN, tap, ci;
    if (g < 9) { w = w0; CIN = 64; tap = g; ci = kk; }
    else { int l = g - 9; w = w1; CIN = 128; tap = l % 9; ci = (l / 9) * 64 + kk; }
    float v = w[(co * CIN + ci) * 9 + tap];
    __nv_bfloat16 hi = __float2bfloat16(v);
    __nv_bfloat16 lo = __float2bfloat16(v - __bfloat162float(hi));
    g_Bh[e] = hi;
    g_Bl[e] = lo;
}

// ---------------- smem layout (bytes) ----------------
// raw bf16 input half, [y=6][x=34][ci=64] padded to 72 ci (144 B rows)
constexpr int SM_RAWH  = 0;
constexpr int RAW_HALF = 29376;             // 6*34*72*2
constexpr int SM_RAWL  = SM_RAWH + RAW_HALF;       // 29376
constexpr int SM_BH0   = 58752;             // 128 rows x 144 B = 18432
constexpr int SM_BH1   = 77184;
constexpr int SM_BL    = 95616;
constexpr int SMEM_BYTES = 114048;
constexpr int SM_EPI   = 0;                 // reuse raw region: 128x132 floats

// ---------------- conv via warp-level bf16 MMA (3-pass split) --------------
// CTA = (4-row px tile, co half, image bs). 256 threads / 8 warps.
// CTA tile: D[128 px][128 co]. Warp tile m32 x n64 (4m x 2n warps).
// Pipelined B: Bh double-buffered (prefetched one tap ahead), Bl single-
// buffered, copied at tap start and consumed only in the last MMA pass so
// its latency hides under 128 MMAs of phase A.
template <int CIN, bool XG>
__global__ void __launch_bounds__(256, 2)
conv_mma_kernel(const float* __restrict__ xin, const float* __restrict__ bias) {
    extern __shared__ char smem[];
    const uint32_t sb = smem_u32(smem);
    const int tid = threadIdx.x;
    const int wid = tid >> 5;
    const int lane = tid & 31;
    const int h0 = blockIdx.x * 4;     // 4 image rows
    const int coh = blockIdx.y;        // co half 0..1
    const int bs = blockIdx.z;         // 0..127

    // warp tiling: 4 (m) x 2 (n)
    const int m0 = (wid & 3) * 32;
    const int n0r = (wid >> 2) * 64;
    // ldmatrix lane geometry (validated R6/R8 mapping)
    const int mrowA = (lane & 7) + ((lane >> 3) & 1) * 8;
    const int kcolA = (lane >> 4) * 8;
    const int noffB = (lane & 7) + (lane >> 4) * 8;
    const int koffB = ((lane >> 3) & 1) * 8;
    const int px0 = m0 + mrowA, px1 = px0 + 16;
    const uint32_t aB0 = sb + SM_RAWH +
        (uint32_t)(((px0 >> 5) * 34 + (px0 & 31)) * 144 + kcolA * 2);
    const uint32_t aB1 = sb + SM_RAWH +
        (uint32_t)(((px1 >> 5) * 34 + (px1 & 31)) * 144 + kcolA * 2);
    const uint32_t bLaneOff = (uint32_t)((n0r + noffB) * 144 + koffB * 2);

    float acc[2][8][4];
#pragma unroll
    for (int m = 0; m < 2; m++)
#pragma unroll
        for (int nb = 0; nb < 8; nb++)
#pragma unroll
            for (int j = 0; j < 4; j++) acc[m][nb][j] = 0.0f;

    const int g_first = (CIN == 64) ? 0 : 9;
    const int g_last  = g_first + 9 * (CIN / 64) - 1;

    // ---- prologue: prefetch Bh(first tap) into bh buffer 0 ----
    {
        const uint4* sh = (const uint4*)(g_Bh + g_first * 16384 + coh * 8192);
#pragma unroll
        for (int i = tid; i < 1024; i += 256)
            cp16(sb + SM_BH0 + (i >> 3) * 144 + (i & 7) * 16, sh + i);
    }
    CP_COMMIT();
    int pb = 0;   // which bh buffer holds the CURRENT tap's Bh

#pragma unroll 1
    for (int cih = 0; cih < CIN / 64; cih++) {
        __syncthreads();   // prior MMAs done reading rawh/rawl
        // ---- stage + convert raw half: [y=6][x=34][ci=64] hi/lo bf16 ----
        const float* xb = (XG ? (const float*)g_out0 : xin) +
                          ((size_t)bs * CIN + cih * 64) * 1024;
        for (int i = tid; i < 64 * 204; i += 256) {
            int ci = i / 204;
            int rr = i - ci * 204;
            int y = rr / 34;
            int xc = rr - y * 34;
            int yy = h0 - 1 + y;
            int xx = xc - 1;
            float v = 0.0f;
            if (yy >= 0 && yy < 32 && xx >= 0 && xx < 32)
                v = xb[ci * 1024 + yy * 32 + xx];
            __nv_bfloat16 hi = __float2bfloat16(v);
            __nv_bfloat16 lo = __float2bfloat16(v - __bfloat162float(hi));
            int off = (y * 34 + xc) * 72 + ci;
            ((__nv_bfloat16*)(smem + SM_RAWH))[off] = hi;
            ((__nv_bfloat16*)(smem + SM_RAWL))[off] = lo;
        }

#pragma unroll 1
        for (int tap = 0; tap < 9; tap++) {
            const int g = g_first + cih * 9 + tap;

            // current Bh prefetch complete; publish it (and raw on tap 0)
            CP_WAIT0();
            __syncthreads();

            // ---- issue Bl(g) copy (group L) ----
            {
                const uint4* sl = (const uint4*)(g_Bl + g * 16384 + coh * 8192);
#pragma unroll
                for (int i = tid; i < 1024; i += 256)
                    cp16(sb + SM_BL + (i >> 3) * 144 + (i & 7) * 16, sl + i);
            }
            CP_COMMIT();
            // ---- prefetch Bh(g+1) into the other buffer (group H) ----
            if (g < g_last) {
                const uint4* sh = (const uint4*)(g_Bh + (g + 1) * 16384 + coh * 8192);
                const uint32_t dst = sb + (pb ? SM_BH0 : SM_BH1);
#pragma unroll
                for (int i = tid; i < 1024; i += 256)
                    cp16(dst + (i >> 3) * 144 + (i & 7) * 16, sh + i);
            }
            CP_COMMIT();   // empty group when g == g_last (keeps counts aligned)

            const uint32_t toff = (uint32_t)(((tap / 3) * 34 + (tap % 3)) * 144);
            const uint32_t a0 = aB0 + toff, a1 = aB1 + toff;
            const uint32_t bh = sb + (pb ? SM_BH1 : SM_BH0) + bLaneOff;
            const uint32_t bl = sb + SM_BL + bLaneOff;

            // ---- phase A: (Ah + Al) x Bh, 128 MMAs ----
#pragma unroll
            for (int ks = 0; ks < 4; ks++) {
                const uint32_t kb = ks * 32;
                uint32_t Ah0[4], Ah1[4], Al0[4], Al1[4], Bf[4][4];
                ldmx4(Ah0, a0 + kb);
                ldmx4(Ah1, a1 + kb);
#pragma unroll
                for (int p = 0; p < 4; p++) ldmx4(Bf[p], bh + p * 2304 + kb);
#pragma unroll
                for (int p = 0; p < 4; p++) {
                    mma16816(acc[0][2 * p],     Ah0, Bf[p][0], Bf[p][1]);
                    mma16816(acc[1][2 * p],     Ah1, Bf[p][0], Bf[p][1]);
                    mma16816(acc[0][2 * p + 1], Ah0, Bf[p][2], Bf[p][3]);
                    mma16816(acc[1][2 * p + 1], Ah1, Bf[p][2], Bf[p][3]);
                }
                ldmx4(Al0, a0 + RAW_HALF + kb);
                ldmx4(Al1, a1 + RAW_HALF + kb);
#pragma unroll
                for (int p = 0; p < 4; p++) {
                    mma16816(acc[0][2 * p],     Al0, Bf[p][0], Bf[p][1]);
                    mma16816(acc[1][2 * p],     Al1, Bf[p][0], Bf[p][1]);
                    mma16816(acc[0][2 * p + 1], Al0, Bf[p][2], Bf[p][3]);
                    mma16816(acc[1][2 * p + 1], Al1, Bf[p][2], Bf[p][3]);
                }
            }

            // ---- drain group L (Bh(g+1) may stay in flight), publish Bl ----
            CP_WAIT1();
            __syncthreads();

            // ---- phase B: Ah x Bl, 64 MMAs ----
#pragma unroll
            for (int ks = 0; ks < 4; ks++) {
                const uint32_t kb = ks * 32;
                uint32_t Ah0[4], Ah1[4], Bf[4][4];
                ldmx4(Ah0, a0 + kb);
                ldmx4(Ah1, a1 + kb);
#pragma unroll
                for (int p = 0; p < 4; p++) ldmx4(Bf[p], bl + p * 2304 + kb);
#pragma unroll
                for (int p = 0; p < 4; p++) {
                    mma16816(acc[0][2 * p],     Ah0, Bf[p][0], Bf[p][1]);
                    mma16816(acc[1][2 * p],     Ah1, Bf[p][0], Bf[p][1]);
                    mma16816(acc[0][2 * p + 1], Ah0, Bf[p][2], Bf[p][3]);
                    mma16816(acc[1][2 * p + 1], Ah1, Bf[p][2], Bf[p][3]);
                }
            }
            pb ^= 1;
        }
    }

    // ---- epilogue: acc -> smem [co][px] (stride 132) -> coalesced gmem ----
    CP_WAIT0();        // no cp.async may still target smem (epi overlaps bh0)
    __syncthreads();
    float* epi = (float*)(smem + SM_EPI);
#pragma unroll
    for (int m = 0; m < 2; m++) {
#pragma unroll
        for (int nb = 0; nb < 8; nb++) {
            int co = n0r + nb * 8 + 2 * (lane & 3);
            int px = m0 + m * 16 + (lane >> 2);
            epi[co * 132 + px] = acc[m][nb][0];
            epi[(co + 1) * 132 + px] = acc[m][nb][1];
            epi[co * 132 + px + 8] = acc[m][nb][2];
            epi[(co + 1) * 132 + px + 8] = acc[m][nb][3];
        }
    }
    __syncthreads();
    {
        float* ghb = g_gh + ((size_t)bs * 256 + coh * 128) * 1024 + h0 * 32;
        for (int i = tid; i < 4096; i += 256) {
            int co = i >> 5;
            int p4 = (i & 31) * 4;
            float4 v = *(float4*)(epi + co * 132 + p4);
            float bv = __ldg(bias + coh * 128 + co);
            v.x += bv; v.y += bv; v.z += bv; v.w += bv;
            *(float4*)(ghb + (size_t)co * 1024 + p4) = v;
        }
    }
}

// ---------------- minGRU sequential scan over S=32 -------------------------
template <int LAYER>
__global__ void scan_kernel(float* __restrict__ dout) {
    int u = blockIdx.x * 256 + threadIdx.x;   // (b, c, p)
    int p = u & 1023;
    int c = (u >> 10) & 127;
    int b = u >> 17;

    const float* gptr = g_gh + ((size_t)(b * 32) * 256 + c) * 1024 + p;
    float* optr = (LAYER == 0 ? g_out0 : dout) +
                  ((size_t)(b * 32) * 128 + c) * 1024 + p;

    float h = 0.5f;
#pragma unroll 4
    for (int s = 0; s < 32; s++) {
        float gate = gptr[0];
        float hd = gptr[131072];
        gptr += 262144;
        float z = 1.0f / (1.0f + __expf(-gate));
        float g = (hd >= 0.0f) ? (hd + 0.5f) : 1.0f / (1.0f + __expf(-hd));
        h += z * (g - h);
        *optr = h;
        optr += 131072;
    }
    dout[16777216 + LAYER * 524288 + u] = h;
}

// ---------------- launch ----------------
extern "C" void kernel_launch(void* const* d_in, const int* in_sizes, int n_in,
                              void* d_out, int out_size) {
    const float* x  = (const float*)d_in[0];
    const float* w0 = (const float*)d_in[1];
    const float* b0 = (const float*)d_in[2];
    const float* w1 = (const float*)d_in[3];
    const float* b1 = (const float*)d_in[4];
    float* out = (float*)d_out;

    cudaFuncSetAttribute(conv_mma_kernel<64, false>,
                         cudaFuncAttributeMaxDynamicSharedMemorySize, SMEM_BYTES);
    cudaFuncSetAttribute(conv_mma_kernel<128, true>,
                         cudaFuncAttributeMaxDynamicSharedMemorySize, SMEM_BYTES);

    prep_kernel<<<1728, 256>>>(w0, w1);
    conv_mma_kernel<64, false><<<dim3(8, 2, 128), 256, SMEM_BYTES>>>(x, b0);
    scan_kernel<0><<<2048, 256>>>(out);
    conv_mma_kernel<128, true><<<dim3(8, 2, 128), 256, SMEM_BYTES>>>(nullptr, b1);
    scan_kernel<1><<<2048, 256>>>(out);
}

// round 11
// speedup vs baseline: 4.8173x; 1.2972x over previous
#include <cuda_runtime.h>
#include <cuda_fp16.h>
#include <cstdint>

// ---------------- scratch (no allocations allowed) ----------------
// gh buffer: layout [bs=128][co=256][px=1024] fp32
__device__ float g_gh[33554432];     // 128 MB
// layer-0 output: [bs=128][c=128][px=1024]
__device__ float g_out0[16777216];   // 64 MB
// prepped fp16 weight chunks: 27 chunks x [256 co][64 k]
__device__ __align__(16) __half g_B[442368];

// ---------------- warp MMA helpers (baseline sm_80+ instructions) ----------
__device__ __forceinline__ uint32_t smem_u32(const void* p) {
    uint32_t a;
    asm("{ .reg .u64 t; cvta.to.shared.u64 t, %1; cvt.u32.u64 %0, t; }"
        : "=r"(a) : "l"(p));
    return a;
}
__device__ __forceinline__ void ldmx4(uint32_t* r, uint32_t a) {
    asm volatile("ldmatrix.sync.aligned.m8n8.x4.shared.b16 {%0,%1,%2,%3}, [%4];"
                 : "=r"(r[0]), "=r"(r[1]), "=r"(r[2]), "=r"(r[3]) : "r"(a));
}
__device__ __forceinline__ void mma16816(float* c, const uint32_t* a,
                                         uint32_t b0, uint32_t b1) {
    asm volatile(
        "mma.sync.aligned.m16n8k16.row.col.f32.f16.f16.f32 "
        "{%0,%1,%2,%3}, {%4,%5,%6,%7}, {%8,%9}, {%0,%1,%2,%3};"
        : "+f"(c[0]), "+f"(c[1]), "+f"(c[2]), "+f"(c[3])
        : "r"(a[0]), "r"(a[1]), "r"(a[2]), "r"(a[3]), "r"(b0), "r"(b1));
}
__device__ __forceinline__ void cp16(uint32_t d, const void* s) {
    asm volatile("cp.async.cg.shared.global [%0], [%1], 16;" :: "r"(d), "l"(s));
}
#define CP_COMMIT() asm volatile("cp.async.commit_group;" ::: "memory")
#define CP_WAIT0()  asm volatile("cp.async.wait_group 0;" ::: "memory")

// ---------------- weight prep: fp16 chunks [g][co][kk] ---------------------
// g<9: layer0 (CIN=64), tap=g, ci=kk. g>=9: layer1, l=g-9, cihalf=l/9,
// tap=l%9, ci=cihalf*64+kk.  For CIN=128, g is consecutive over (cih, tap)
// in exactly the kernel's iteration order.
__global__ void prep_kernel(const float* __restrict__ w0,
                            const float* __restrict__ w1) {
    int e = blockIdx.x * 256 + threadIdx.x;   // grid = 1728 -> 442368 exact
    int g = e >> 14;
    int rem = e & 16383;
    int co = rem >> 6;
    int kk = rem & 63;
    const float* w;
    int CIN, tap, ci;
    if (g < 9) { w = w0; CIN = 64; tap = g; ci = kk; }
    else { int l = g - 9; w = w1; CIN = 128; tap = l % 9; ci = (l / 9) * 64 + kk; }
    g_B[e] = __float2half_rn(w[(co * CIN + ci) * 9 + tap]);
}

// ---------------- smem layout (bytes) ----------------
// raw fp16 input half, [y=6][x=34][ci=64] padded to 72 ci (144 B rows),
// hi and lo parts of the fp16 split of x.
constexpr int SM_RAWH  = 0;
constexpr int RAW_HALF = 29376;             // 6*34*72*2
constexpr int SM_RAWL  = SM_RAWH + RAW_HALF;       // 29376
constexpr int SM_B0    = 58752;             // 128 rows x 144 B = 18432
constexpr int SM_B1    = 77184;
constexpr int SMEM_BYTES = 95616;
constexpr int SM_EPI   = 0;                 // reuse raw region: 128x132 floats

// ---------------- conv via warp-level fp16 MMA (2-pass split) --------------
// CTA = (4-row px tile, co half, image bs). 256 threads / 8 warps.
// CTA tile: D[128 px][128 co]. Warp tile m32 x n64 (4m x 2n warps).
// D = xh*wh + xl*wh; omitted x*(w-wh) ~ 2^-11 (measured-anchor ~5e-4 rel).
// B double-buffered across taps: prefetch next tap's B during current MMAs.
template <int CIN, bool XG>
__global__ void __launch_bounds__(256, 2)
conv_mma_kernel(const float* __restrict__ xin, const float* __restrict__ bias) {
    extern __shared__ char smem[];
    const uint32_t sb = smem_u32(smem);
    const int tid = threadIdx.x;
    const int wid = tid >> 5;
    const int lane = tid & 31;
    const int h0 = blockIdx.x * 4;     // 4 image rows
    const int coh = blockIdx.y;        // co half 0..1
    const int bs = blockIdx.z;         // 0..127

    // warp tiling: 4 (m) x 2 (n)
    const int m0 = (wid & 3) * 32;
    const int n0r = (wid >> 2) * 64;
    // ldmatrix lane geometry (validated R6/R8 mapping)
    const int mrowA = (lane & 7) + ((lane >> 3) & 1) * 8;
    const int kcolA = (lane >> 4) * 8;
    const int noffB = (lane & 7) + (lane >> 4) * 8;
    const int koffB = ((lane >> 3) & 1) * 8;
    const int px0 = m0 + mrowA, px1 = px0 + 16;
    const uint32_t aB0 = sb + SM_RAWH +
        (uint32_t)(((px0 >> 5) * 34 + (px0 & 31)) * 144 + kcolA * 2);
    const uint32_t aB1 = sb + SM_RAWH +
        (uint32_t)(((px1 >> 5) * 34 + (px1 & 31)) * 144 + kcolA * 2);
    const uint32_t bLaneOff = (uint32_t)((n0r + noffB) * 144 + koffB * 2);

    float acc[2][8][4];
#pragma unroll
    for (int m = 0; m < 2; m++)
#pragma unroll
        for (int nb = 0; nb < 8; nb++)
#pragma unroll
            for (int j = 0; j < 4; j++) acc[m][nb][j] = 0.0f;

    const int g_first = (CIN == 64) ? 0 : 9;
    const int g_last  = g_first + 9 * (CIN / 64) - 1;

    // ---- prologue: prefetch B(first tap) into buffer 0 ----
    {
        const uint4* sB = (const uint4*)(g_B + g_first * 16384 + coh * 8192);
#pragma unroll
        for (int i = tid; i < 1024; i += 256)
            cp16(sb + SM_B0 + (i >> 3) * 144 + (i & 7) * 16, sB + i);
    }
    CP_COMMIT();
    int pb = 0;   // buffer holding the CURRENT tap's B

#pragma unroll 1
    for (int cih = 0; cih < CIN / 64; cih++) {
        __syncthreads();   // prior MMAs done reading rawh/rawl
        // ---- stage + convert raw half: [y=6][x=34][ci=64] fp16 hi/lo ----
        const float* xb = (XG ? (const float*)g_out0 : xin) +
                          ((size_t)bs * CIN + cih * 64) * 1024;
        for (int i = tid; i < 64 * 204; i += 256) {
            int ci = i / 204;
            int rr = i - ci * 204;
            int y = rr / 34;
            int xc = rr - y * 34;
            int yy = h0 - 1 + y;
            int xx = xc - 1;
            float v = 0.0f;
            if (yy >= 0 && yy < 32 && xx >= 0 && xx < 32)
                v = xb[ci * 1024 + yy * 32 + xx];
            __half hi = __float2half_rn(v);
            __half lo = __float2half_rn(v - __half2float(hi));
            int off = (y * 34 + xc) * 72 + ci;
            ((__half*)(smem + SM_RAWH))[off] = hi;
            ((__half*)(smem + SM_RAWL))[off] = lo;
        }

#pragma unroll 1
        for (int tap = 0; tap < 9; tap++) {
            const int g = g_first + cih * 9 + tap;

            // B(g) prefetch (issued a full tap ago) complete; publish it
            // (also publishes raw staging on the first tap of each cih).
            CP_WAIT0();
            __syncthreads();

            // ---- prefetch B(g+1) into the other buffer ----
            if (g < g_last) {
                const uint4* sB = (const uint4*)(g_B + (g + 1) * 16384 + coh * 8192);
                const uint32_t dst = sb + (pb ? SM_B0 : SM_B1);
#pragma unroll
                for (int i = tid; i < 1024; i += 256)
                    cp16(dst + (i >> 3) * 144 + (i & 7) * 16, sB + i);
                CP_COMMIT();
            }

            const uint32_t toff = (uint32_t)(((tap / 3) * 34 + (tap % 3)) * 144);
            const uint32_t a0 = aB0 + toff, a1 = aB1 + toff;
            const uint32_t bB = sb + (pb ? SM_B1 : SM_B0) + bLaneOff;

            // ---- (xh + xl) x wh: 128 MMAs / warp ----
#pragma unroll
            for (int ks = 0; ks < 4; ks++) {
                const uint32_t kb = ks * 32;
                uint32_t Ah0[4], Ah1[4], Al0[4], Al1[4], Bf[4][4];
                ldmx4(Ah0, a0 + kb);
                ldmx4(Ah1, a1 + kb);
#pragma unroll
                for (int p = 0; p < 4; p++) ldmx4(Bf[p], bB + p * 2304 + kb);
#pragma unroll
                for (int p = 0; p < 4; p++) {
                    mma16816(acc[0][2 * p],     Ah0, Bf[p][0], Bf[p][1]);
                    mma16816(acc[1][2 * p],     Ah1, Bf[p][0], Bf[p][1]);
                    mma16816(acc[0][2 * p + 1], Ah0, Bf[p][2], Bf[p][3]);
                    mma16816(acc[1][2 * p + 1], Ah1, Bf[p][2], Bf[p][3]);
                }
                ldmx4(Al0, a0 + RAW_HALF + kb);
                ldmx4(Al1, a1 + RAW_HALF + kb);
#pragma unroll
                for (int p = 0; p < 4; p++) {
                    mma16816(acc[0][2 * p],     Al0, Bf[p][0], Bf[p][1]);
                    mma16816(acc[1][2 * p],     Al1, Bf[p][0], Bf[p][1]);
                    mma16816(acc[0][2 * p + 1], Al0, Bf[p][2], Bf[p][3]);
                    mma16816(acc[1][2 * p + 1], Al1, Bf[p][2], Bf[p][3]);
                }
            }
            pb ^= 1;
        }
    }

    // ---- epilogue: acc -> smem [co][px] (stride 132) -> coalesced gmem ----
    // (no cp.async in flight: last tap issues no prefetch)
    __syncthreads();
    float* epi = (float*)(smem + SM_EPI);
#pragma unroll
    for (int m = 0; m < 2; m++) {
#pragma unroll
        for (int nb = 0; nb < 8; nb++) {
            int co = n0r + nb * 8 + 2 * (lane & 3);
            int px = m0 + m * 16 + (lane >> 2);
            epi[co * 132 + px] = acc[m][nb][0];
            epi[(co + 1) * 132 + px] = acc[m][nb][1];
            epi[co * 132 + px + 8] = acc[m][nb][2];
            epi[(co + 1) * 132 + px + 8] = acc[m][nb][3];
        }
    }
    __syncthreads();
    {
        float* ghb = g_gh + ((size_t)bs * 256 + coh * 128) * 1024 + h0 * 32;
        for (int i = tid; i < 4096; i += 256) {
            int co = i >> 5;
            int p4 = (i & 31) * 4;
            float4 v = *(float4*)(epi + co * 132 + p4);
            float bv = __ldg(bias + coh * 128 + co);
            v.x += bv; v.y += bv; v.z += bv; v.w += bv;
            *(float4*)(ghb + (size_t)co * 1024 + p4) = v;
        }
    }
}

// ---------------- minGRU sequential scan over S=32 -------------------------
template <int LAYER>
__global__ void scan_kernel(float* __restrict__ dout) {
    int u = blockIdx.x * 256 + threadIdx.x;   // (b, c, p)
    int p = u & 1023;
    int c = (u >> 10) & 127;
    int b = u >> 17;

    const float* gptr = g_gh + ((size_t)(b * 32) * 256 + c) * 1024 + p;
    float* optr = (LAYER == 0 ? g_out0 : dout) +
                  ((size_t)(b * 32) * 128 + c) * 1024 + p;

    float h = 0.5f;
#pragma unroll 4
    for (int s = 0; s < 32; s++) {
        float gate = gptr[0];
        float hd = gptr[131072];
        gptr += 262144;
        float z = 1.0f / (1.0f + __expf(-gate));
        float g = (hd >= 0.0f) ? (hd + 0.5f) : 1.0f / (1.0f + __expf(-hd));
        h += z * (g - h);
        *optr = h;
        optr += 131072;
    }
    dout[16777216 + LAYER * 524288 + u] = h;
}

// ---------------- launch ----------------
extern "C" void kernel_launch(void* const* d_in, const int* in_sizes, int n_in,
                              void* d_out, int out_size) {
    const float* x  = (const float*)d_in[0];
    const float* w0 = (const float*)d_in[1];
    const float* b0 = (const float*)d_in[2];
    const float* w1 = (const float*)d_in[3];
    const float* b1 = (const float*)d_in[4];
    float* out = (float*)d_out;

    cudaFuncSetAttribute(conv_mma_kernel<64, false>,
                         cudaFuncAttributeMaxDynamicSharedMemorySize, SMEM_BYTES);
    cudaFuncSetAttribute(conv_mma_kernel<128, true>,
                         cudaFuncAttributeMaxDynamicSharedMemorySize, SMEM_BYTES);

    prep_kernel<<<1728, 256>>>(w0, w1);
    conv_mma_kernel<64, false><<<dim3(8, 2, 128), 256, SMEM_BYTES>>>(x, b0);
    scan_kernel<0><<<2048, 256>>>(out);
    conv_mma_kernel<128, true><<<dim3(8, 2, 128), 256, SMEM_BYTES>>>(nullptr, b1);
    scan_kernel<1><<<2048, 256>>>(out);
}

// round 12
// speedup vs baseline: 6.3254x; 1.3131x over previous
#include <cuda_runtime.h>
#include <cuda_fp16.h>
#include <cstdint>

// ---------------- scratch (no allocations allowed) ----------------
// gh buffer: layout [bs=128][co=256][px=1024] fp32
__device__ float g_gh[33554432];     // 128 MB
// layer-0 output: [bs=128][c=128][px=1024]
__device__ float g_out0[16777216];   // 64 MB
// prepped fp16 weight chunks: 27 chunks x [256 co][64 k]
__device__ __align__(16) __half g_B[442368];

// ---------------- warp MMA helpers (baseline sm_80+ instructions) ----------
__device__ __forceinline__ uint32_t smem_u32(const void* p) {
    uint32_t a;
    asm("{ .reg .u64 t; cvta.to.shared.u64 t, %1; cvt.u32.u64 %0, t; }"
        : "=r"(a) : "l"(p));
    return a;
}
__device__ __forceinline__ void ldmx4(uint32_t* r, uint32_t a) {
    asm volatile("ldmatrix.sync.aligned.m8n8.x4.shared.b16 {%0,%1,%2,%3}, [%4];"
                 : "=r"(r[0]), "=r"(r[1]), "=r"(r[2]), "=r"(r[3]) : "r"(a));
}
__device__ __forceinline__ void mma16816(float* c, const uint32_t* a,
                                         uint32_t b0, uint32_t b1) {
    asm volatile(
        "mma.sync.aligned.m16n8k16.row.col.f32.f16.f16.f32 "
        "{%0,%1,%2,%3}, {%4,%5,%6,%7}, {%8,%9}, {%0,%1,%2,%3};"
        : "+f"(c[0]), "+f"(c[1]), "+f"(c[2]), "+f"(c[3])
        : "r"(a[0]), "r"(a[1]), "r"(a[2]), "r"(a[3]), "r"(b0), "r"(b1));
}
__device__ __forceinline__ void cp16(uint32_t d, const void* s) {
    asm volatile("cp.async.cg.shared.global [%0], [%1], 16;" :: "r"(d), "l"(s));
}
#define CP_COMMIT() asm volatile("cp.async.commit_group;" ::: "memory")
#define CP_WAIT0()  asm volatile("cp.async.wait_group 0;" ::: "memory")

// ---------------- weight prep: fp16 chunks [g][co][kk] ---------------------
// g<9: layer0 (CIN=64), tap=g, ci=kk. g>=9: layer1, l=g-9, cihalf=l/9,
// tap=l%9, ci=cihalf*64+kk.  For CIN=128, g is consecutive over (cih, tap)
// in exactly the kernel's iteration order.
__global__ void prep_kernel(const float* __restrict__ w0,
                            const float* __restrict__ w1) {
    int e = blockIdx.x * 256 + threadIdx.x;   // grid = 1728 -> 442368 exact
    int g = e >> 14;
    int rem = e & 16383;
    int co = rem >> 6;
    int kk = rem & 63;
    const float* w;
    int CIN, tap, ci;
    if (g < 9) { w = w0; CIN = 64; tap = g; ci = kk; }
    else { int l = g - 9; w = w1; CIN = 128; tap = l % 9; ci = (l / 9) * 64 + kk; }
    g_B[e] = __float2half_rn(w[(co * CIN + ci) * 9 + tap]);
}

// ---------------- smem layout (bytes) ----------------
// raw fp16 input half, [y=6][x=34][ci=64] padded to 72 ci (144 B rows)
constexpr int SM_RAW   = 0;
constexpr int RAW_SZ   = 29376;             // 6*34*72*2
constexpr int SM_B0    = 29376;             // 128 rows x 144 B = 18432
constexpr int SM_B1    = 47808;
constexpr int SM_EPI   = 0;                 // reuse: 128 x 132 floats = 67584
constexpr int SMEM_BYTES = 67584;           // max(layout end 66240, epi 67584)

// ---------------- conv via warp-level fp16 MMA (single pass) ---------------
// CTA = (4-row px tile, co half, image bs). 256 threads / 8 warps.
// CTA tile: D[128 px][128 co]. Warp tile m32 x n64 (4m x 2n warps).
// D = fp16(x) * fp16(w); omitted half-ulp terms give ~1.9e-4 rel error
// (anchored on R11's measured 1.35e-4 for one omitted term).
// B double-buffered across taps: prefetch next tap's B during current MMAs.
template <int CIN, bool XG>
__global__ void __launch_bounds__(256, 2)
conv_mma_kernel(const float* __restrict__ xin, const float* __restrict__ bias) {
    extern __shared__ char smem[];
    const uint32_t sb = smem_u32(smem);
    const int tid = threadIdx.x;
    const int wid = tid >> 5;
    const int lane = tid & 31;
    const int h0 = blockIdx.x * 4;     // 4 image rows
    const int coh = blockIdx.y;        // co half 0..1
    const int bs = blockIdx.z;         // 0..127

    // warp tiling: 4 (m) x 2 (n)
    const int m0 = (wid & 3) * 32;
    const int n0r = (wid >> 2) * 64;
    // ldmatrix lane geometry (validated R6/R8 mapping)
    const int mrowA = (lane & 7) + ((lane >> 3) & 1) * 8;
    const int kcolA = (lane >> 4) * 8;
    const int noffB = (lane & 7) + (lane >> 4) * 8;
    const int koffB = ((lane >> 3) & 1) * 8;
    const int px0 = m0 + mrowA, px1 = px0 + 16;
    const uint32_t aB0 = sb + SM_RAW +
        (uint32_t)(((px0 >> 5) * 34 + (px0 & 31)) * 144 + kcolA * 2);
    const uint32_t aB1 = sb + SM_RAW +
        (uint32_t)(((px1 >> 5) * 34 + (px1 & 31)) * 144 + kcolA * 2);
    const uint32_t bLaneOff = (uint32_t)((n0r + noffB) * 144 + koffB * 2);

    float acc[2][8][4];
#pragma unroll
    for (int m = 0; m < 2; m++)
#pragma unroll
        for (int nb = 0; nb < 8; nb++)
#pragma unroll
            for (int j = 0; j < 4; j++) acc[m][nb][j] = 0.0f;

    const int g_first = (CIN == 64) ? 0 : 9;
    const int g_last  = g_first + 9 * (CIN / 64) - 1;

    // ---- prologue: prefetch B(first tap) into buffer 0 ----
    {
        const uint4* sB = (const uint4*)(g_B + g_first * 16384 + coh * 8192);
#pragma unroll
        for (int i = tid; i < 1024; i += 256)
            cp16(sb + SM_B0 + (i >> 3) * 144 + (i & 7) * 16, sB + i);
    }
    CP_COMMIT();
    int pb = 0;   // buffer holding the CURRENT tap's B

#pragma unroll 1
    for (int cih = 0; cih < CIN / 64; cih++) {
        __syncthreads();   // prior MMAs done reading raw
        // ---- stage + convert raw half: [y=6][x=34][ci=64] fp16 ----
        const float* xb = (XG ? (const float*)g_out0 : xin) +
                          ((size_t)bs * CIN + cih * 64) * 1024;
        for (int i = tid; i < 64 * 204; i += 256) {
            int ci = i / 204;
            int rr = i - ci * 204;
            int y = rr / 34;
            int xc = rr - y * 34;
            int yy = h0 - 1 + y;
            int xx = xc - 1;
            float v = 0.0f;
            if (yy >= 0 && yy < 32 && xx >= 0 && xx < 32)
                v = xb[ci * 1024 + yy * 32 + xx];
            ((__half*)(smem + SM_RAW))[(y * 34 + xc) * 72 + ci] =
                __float2half_rn(v);
        }

#pragma unroll 1
        for (int tap = 0; tap < 9; tap++) {
            const int g = g_first + cih * 9 + tap;

            // B(g) prefetch (issued a full tap ago) complete; publish it
            // (also publishes raw staging on the first tap of each cih).
            CP_WAIT0();
            __syncthreads();

            // ---- prefetch B(g+1) into the other buffer ----
            if (g < g_last) {
                const uint4* sB = (const uint4*)(g_B + (g + 1) * 16384 + coh * 8192);
                const uint32_t dst = sb + (pb ? SM_B0 : SM_B1);
#pragma unroll
                for (int i = tid; i < 1024; i += 256)
                    cp16(dst + (i >> 3) * 144 + (i & 7) * 16, sB + i);
                CP_COMMIT();
            }

            const uint32_t toff = (uint32_t)(((tap / 3) * 34 + (tap % 3)) * 144);
            const uint32_t a0 = aB0 + toff, a1 = aB1 + toff;
            const uint32_t bB = sb + (pb ? SM_B1 : SM_B0) + bLaneOff;

            // ---- xh x wh: 64 MMAs / warp ----
#pragma unroll
            for (int ks = 0; ks < 4; ks++) {
                const uint32_t kb = ks * 32;
                uint32_t Ah0[4], Ah1[4], Bf[4][4];
                ldmx4(Ah0, a0 + kb);
                ldmx4(Ah1, a1 + kb);
#pragma unroll
                for (int p = 0; p < 4; p++) ldmx4(Bf[p], bB + p * 2304 + kb);
#pragma unroll
                for (int p = 0; p < 4; p++) {
                    mma16816(acc[0][2 * p],     Ah0, Bf[p][0], Bf[p][1]);
                    mma16816(acc[1][2 * p],     Ah1, Bf[p][0], Bf[p][1]);
                    mma16816(acc[0][2 * p + 1], Ah0, Bf[p][2], Bf[p][3]);
                    mma16816(acc[1][2 * p + 1], Ah1, Bf[p][2], Bf[p][3]);
                }
            }
            pb ^= 1;
        }
    }

    // ---- epilogue: acc -> smem [co][px] (stride 132) -> coalesced gmem ----
    // (no cp.async in flight: last tap issues no prefetch)
    __syncthreads();
    float* epi = (float*)(smem + SM_EPI);
#pragma unroll
    for (int m = 0; m < 2; m++) {
#pragma unroll
        for (int nb = 0; nb < 8; nb++) {
            int co = n0r + nb * 8 + 2 * (lane & 3);
            int px = m0 + m * 16 + (lane >> 2);
            epi[co * 132 + px] = acc[m][nb][0];
            epi[(co + 1) * 132 + px] = acc[m][nb][1];
            epi[co * 132 + px + 8] = acc[m][nb][2];
            epi[(co + 1) * 132 + px + 8] = acc[m][nb][3];
        }
    }
    __syncthreads();
    {
        float* ghb = g_gh + ((size_t)bs * 256 + coh * 128) * 1024 + h0 * 32;
        for (int i = tid; i < 4096; i += 256) {
            int co = i >> 5;
            int p4 = (i & 31) * 4;
            float4 v = *(float4*)(epi + co * 132 + p4);
            float bv = __ldg(bias + coh * 128 + co);
            v.x += bv; v.y += bv; v.z += bv; v.w += bv;
            *(float4*)(ghb + (size_t)co * 1024 + p4) = v;
        }
    }
}

// ---------------- minGRU sequential scan over S=32 -------------------------
template <int LAYER>
__global__ void scan_kernel(float* __restrict__ dout) {
    int u = blockIdx.x * 256 + threadIdx.x;   // (b, c, p)
    int p = u & 1023;
    int c = (u >> 10) & 127;
    int b = u >> 17;

    const float* gptr = g_gh + ((size_t)(b * 32) * 256 + c) * 1024 + p;
    float* optr = (LAYER == 0 ? g_out0 : dout) +
                  ((size_t)(b * 32) * 128 + c) * 1024 + p;

    float h = 0.5f;
#pragma unroll 4
    for (int s = 0; s < 32; s++) {
        float gate = gptr[0];
        float hd = gptr[131072];
        gptr += 262144;
        float z = 1.0f / (1.0f + __expf(-gate));
        float g = (hd >= 0.0f) ? (hd + 0.5f) : 1.0f / (1.0f + __expf(-hd));
        h += z * (g - h);
        *optr = h;
        optr += 131072;
    }
    dout[16777216 + LAYER * 524288 + u] = h;
}

// ---------------- launch ----------------
extern "C" void kernel_launch(void* const* d_in, const int* in_sizes, int n_in,
                              void* d_out, int out_size) {
    const float* x  = (const float*)d_in[0];
    const float* w0 = (const float*)d_in[1];
    const float* b0 = (const float*)d_in[2];
    const float* w1 = (const float*)d_in[3];
    const float* b1 = (const float*)d_in[4];
    float* out = (float*)d_out;

    cudaFuncSetAttribute(conv_mma_kernel<64, false>,
                         cudaFuncAttributeMaxDynamicSharedMemorySize, SMEM_BYTES);
    cudaFuncSetAttribute(conv_mma_kernel<128, true>,
                         cudaFuncAttributeMaxDynamicSharedMemorySize, SMEM_BYTES);

    prep_kernel<<<1728, 256>>>(w0, w1);
    conv_mma_kernel<64, false><<<dim3(8, 2, 128), 256, SMEM_BYTES>>>(x, b0);
    scan_kernel<0><<<2048, 256>>>(out);
    conv_mma_kernel<128, true><<<dim3(8, 2, 128), 256, SMEM_BYTES>>>(nullptr, b1);
    scan_kernel<1><<<2048, 256>>>(out);
}

// round 13
// speedup vs baseline: 7.3263x; 1.1582x over previous
#include <cuda_runtime.h>
#include <cuda_fp16.h>
#include <cstdint>

// ---------------- scratch (no allocations allowed) ----------------
__device__ float g_gh[33554432];                    // [bs=128][px=1024][co=256] fp32
__device__ __align__(16) __half g_xh[8388608];      // [bs][px][ci=64] fp16
__device__ __align__(16) __half g_out0h[16777216];  // [bs][px][ci=128] fp16
__device__ __align__(16) __half g_B[442368];        // 27 chunks x [256 co][64 k]
__device__ uint4 g_zero[8] = {};                    // 128 B zeros (halo cp source)

// ---------------- warp MMA helpers (baseline sm_80+ instructions) ----------
__device__ __forceinline__ uint32_t smem_u32(const void* p) {
    uint32_t a;
    asm("{ .reg .u64 t; cvta.to.shared.u64 t, %1; cvt.u32.u64 %0, t; }"
        : "=r"(a) : "l"(p));
    return a;
}
__device__ __forceinline__ void ldmx4(uint32_t* r, uint32_t a) {
    asm volatile("ldmatrix.sync.aligned.m8n8.x4.shared.b16 {%0,%1,%2,%3}, [%4];"
                 : "=r"(r[0]), "=r"(r[1]), "=r"(r[2]), "=r"(r[3]) : "r"(a));
}
__device__ __forceinline__ void mma16816(float* c, const uint32_t* a,
                                         uint32_t b0, uint32_t b1) {
    asm volatile(
        "mma.sync.aligned.m16n8k16.row.col.f32.f16.f16.f32 "
        "{%0,%1,%2,%3}, {%4,%5,%6,%7}, {%8,%9}, {%0,%1,%2,%3};"
        : "+f"(c[0]), "+f"(c[1]), "+f"(c[2]), "+f"(c[3])
        : "r"(a[0]), "r"(a[1]), "r"(a[2]), "r"(a[3]), "r"(b0), "r"(b1));
}
__device__ __forceinline__ void cp16(uint32_t d, const void* s) {
    asm volatile("cp.async.cg.shared.global [%0], [%1], 16;" :: "r"(d), "l"(s));
}
#define CP_COMMIT() asm volatile("cp.async.commit_group;" ::: "memory")
#define CP_WAIT0()  asm volatile("cp.async.wait_group 0;" ::: "memory")

// ---------------- weight prep: fp16 chunks [g][co][kk] ---------------------
__global__ void prep_w_kernel(const float* __restrict__ w0,
                              const float* __restrict__ w1) {
    int e = blockIdx.x * 256 + threadIdx.x;   // grid = 1728 -> 442368 exact
    int g = e >> 14;
    int rem = e & 16383;
    int co = rem >> 6;
    int kk = rem & 63;
    const float* w;
    int CIN, tap, ci;
    if (g < 9) { w = w0; CIN = 64; tap = g; ci = kk; }
    else { int l = g - 9; w = w1; CIN = 128; tap = l % 9; ci = (l / 9) * 64 + kk; }
    g_B[e] = __float2half_rn(w[(co * CIN + ci) * 9 + tap]);
}

// ---------------- x prep: [bs][ci=64][px] fp32 -> [bs][px][ci] fp16 --------
__global__ void prep_x_kernel(const float* __restrict__ x) {
    __shared__ __half sm[128 * 72];   // [p 0..127][ci pad 72]
    const int bs = blockIdx.x, pxb = blockIdx.y;   // grid (128, 8)
    const int tid = threadIdx.x;
    const float* xb = x + (size_t)bs * 65536 + pxb * 128;
#pragma unroll
    for (int k = 0; k < 32; k++) {
        int i = tid + k * 256;        // 8192 = 64 ci * 128 px
        int ci = i >> 7, p = i & 127;
        sm[p * 72 + ci] = __float2half_rn(xb[ci * 1024 + p]);
    }
    __syncthreads();
    uint4* dst = (uint4*)(g_xh + (size_t)bs * 65536 + (size_t)pxb * 128 * 64);
#pragma unroll
    for (int k = 0; k < 4; k++) {
        int i = tid + k * 256;        // 1024 = 128 px * 8 segs
        int p = i >> 3, seg = i & 7;
        dst[p * 8 + seg] = *(uint4*)(sm + p * 72 + seg * 8);
    }
}

// ---------------- smem layout (bytes) ----------------
constexpr int RAW_SZ = 29376;       // 204 rows x 144 B ([y*34+x][ci 64 pad 72])
// conv0: RAW0 | B0 | B1          (B at 29376 / 47808), total 67584 (epi)
// conv1: RAW0 | RAW1 | B0 | B1   (B at 58752 / 77184), total 95616
constexpr int B_SZ = 18432;

// ---------------- conv via warp-level fp16 MMA -----------------------------
// CTA = (4-row px tile, co half, image bs). 256 threads / 8 warps.
// CTA tile: D[128 px][128 co]. Warp tile m32 x n64 (4m x 2n warps).
// All A staging is cp.async from px-major fp16 sources; raw double-buffered
// across cih halves (conv1); B double-buffered across taps.
template <int CIN, bool XG>
__global__ void __launch_bounds__(256, 2)
conv_mma_kernel(const float* __restrict__ bias) {
    extern __shared__ char smem[];
    const uint32_t sb = smem_u32(smem);
    const int tid = threadIdx.x;
    const int wid = tid >> 5;
    const int lane = tid & 31;
    const int h0 = blockIdx.x * 4;     // 4 image rows
    const int coh = blockIdx.y;        // co half 0..1
    const int bs = blockIdx.z;         // 0..127

    const uint32_t SMB0 = (CIN == 64) ? 29376u : 58752u;
    const uint32_t SMB1 = SMB0 + B_SZ;

    // px-major fp16 activation source; stride halves per px
    const __half* src = XG ? (g_out0h + (size_t)bs * 131072)
                           : (g_xh + (size_t)bs * 65536);
    const int SRC_STRIDE = XG ? 128 : 64;

    // warp tiling: 4 (m) x 2 (n)
    const int m0 = (wid & 3) * 32;
    const int n0r = (wid >> 2) * 64;
    // ldmatrix lane geometry (validated mapping)
    const int mrowA = (lane & 7) + ((lane >> 3) & 1) * 8;
    const int kcolA = (lane >> 4) * 8;
    const int noffB = (lane & 7) + (lane >> 4) * 8;
    const int koffB = ((lane >> 3) & 1) * 8;
    const int px0 = m0 + mrowA, px1 = px0 + 16;
    const uint32_t aB0 = sb +
        (uint32_t)(((px0 >> 5) * 34 + (px0 & 31)) * 144 + kcolA * 2);
    const uint32_t aB1 = sb +
        (uint32_t)(((px1 >> 5) * 34 + (px1 & 31)) * 144 + kcolA * 2);
    const uint32_t bLaneOff = (uint32_t)((n0r + noffB) * 144 + koffB * 2);

    float acc[2][8][4];
#pragma unroll
    for (int m = 0; m < 2; m++)
#pragma unroll
        for (int nb = 0; nb < 8; nb++)
#pragma unroll
            for (int j = 0; j < 4; j++) acc[m][nb][j] = 0.0f;

    const int g_first = (CIN == 64) ? 0 : 9;
    const int g_last  = g_first + 9 * (CIN / 64) - 1;

    // ---- raw staging via cp.async: dst raw buffer, ci-half hh ----
    auto stage_raw = [&](uint32_t dst, int hh) {
        const __half* s0 = src + hh * 64;
        for (int i = tid; i < 1632; i += 256) {      // 204 rows x 8 segs
            int row = i >> 3, seg = i & 7;
            int y = row / 34, xc = row - y * 34;
            int yy = h0 - 1 + y, xx = xc - 1;
            const void* sp = g_zero;
            if (yy >= 0 && yy < 32 && xx >= 0 && xx < 32)
                sp = s0 + (size_t)(yy * 32 + xx) * SRC_STRIDE + seg * 8;
            cp16(dst + row * 144 + seg * 16, sp);
        }
    };
    auto copy_B = [&](int g, uint32_t dst) {
        const uint4* sB = (const uint4*)(g_B + g * 16384 + coh * 8192);
#pragma unroll
        for (int i = tid; i < 1024; i += 256)
            cp16(dst + (i >> 3) * 144 + (i & 7) * 16, sB + i);
    };

    // ---- prologue: stage raw(cih0) + B(first tap), one group ----
    stage_raw(sb + 0, 0);
    copy_B(g_first, sb + SMB0);
    CP_COMMIT();
    int pb = 0;   // buffer holding the CURRENT tap's B

#pragma unroll 1
    for (int cih = 0; cih < CIN / 64; cih++) {
#pragma unroll 1
        for (int tap = 0; tap < 9; tap++) {
            const int g = g_first + cih * 9 + tap;

            CP_WAIT0();        // current B (and raw groups) complete
            __syncthreads();

            if (XG && g == g_first) {
                // prefetch raw(cih1) + B(next) together, covered by this tap
                stage_raw(sb + RAW_SZ, 1);
                copy_B(g + 1, sb + (pb ? SMB0 : SMB1));
                CP_COMMIT();
            } else if (g < g_last) {
                copy_B(g + 1, sb + (pb ? SMB0 : SMB1));
                CP_COMMIT();
            }

            const uint32_t roff = (uint32_t)(cih * RAW_SZ) +
                (uint32_t)(((tap / 3) * 34 + (tap % 3)) * 144);
            const uint32_t a0 = aB0 + roff, a1 = aB1 + roff;
            const uint32_t bB = sb + (pb ? SMB1 : SMB0) + bLaneOff;

            // ---- 64 MMAs / warp ----
#pragma unroll
            for (int ks = 0; ks < 4; ks++) {
                const uint32_t kb = ks * 32;
                uint32_t Ah0[4], Ah1[4], Bf[4][4];
                ldmx4(Ah0, a0 + kb);
                ldmx4(Ah1, a1 + kb);
#pragma unroll
                for (int p = 0; p < 4; p++) ldmx4(Bf[p], bB + p * 2304 + kb);
#pragma unroll
                for (int p = 0; p < 4; p++) {
                    mma16816(acc[0][2 * p],     Ah0, Bf[p][0], Bf[p][1]);
                    mma16816(acc[1][2 * p],     Ah1, Bf[p][0], Bf[p][1]);
                    mma16816(acc[0][2 * p + 1], Ah0, Bf[p][2], Bf[p][3]);
                    mma16816(acc[1][2 * p + 1], Ah1, Bf[p][2], Bf[p][3]);
                }
            }
            pb ^= 1;
        }
    }

    // ---- epilogue: acc -> epi[px][co] (pitch 132 floats) -> gh px-major ----
    __syncthreads();
    float* epi = (float*)smem;
#pragma unroll
    for (int m = 0; m < 2; m++) {
#pragma unroll
        for (int nb = 0; nb < 8; nb++) {
            int px = m0 + m * 16 + (lane >> 2);
            int co = n0r + nb * 8 + 2 * (lane & 3);
            *(float2*)(epi + px * 132 + co) =
                make_float2(acc[m][nb][0], acc[m][nb][1]);
            *(float2*)(epi + (px + 8) * 132 + co) =
                make_float2(acc[m][nb][2], acc[m][nb][3]);
        }
    }
    __syncthreads();
    {
        float* ghb = g_gh + ((size_t)bs * 1024 + h0 * 32) * 256 + coh * 128;
        const float4* bv4 = (const float4*)(bias + coh * 128);
        for (int i = tid; i < 4096; i += 256) {
            int px = i >> 5, c4 = i & 31;
            float4 v = *(float4*)(epi + px * 132 + c4 * 4);
            float4 bv = __ldg(bv4 + c4);
            v.x += bv.x; v.y += bv.y; v.z += bv.z; v.w += bv.w;
            *(float4*)(ghb + (size_t)px * 256 + c4 * 4) = v;
        }
    }
}

// ---------------- scan 0: gh px-major -> fp16 out0 + finals slot 0 ---------
__global__ void scan0_kernel(float* __restrict__ dout) {
    const int tid = threadIdx.x;
    const int blk = blockIdx.x;           // 2048
    const int b = blk >> 9, pxb = blk & 511;
    const int px = pxb * 2 + (tid >> 7);
    const int c = tid & 127;

    const float* gb = g_gh + ((size_t)(b * 32) * 1024 + px) * 256 + c;
    __half* ob = g_out0h + ((size_t)(b * 32) * 1024 + px) * 128 + c;

    float h = 0.5f;
#pragma unroll 4
    for (int s = 0; s < 32; s++) {
        float gate = gb[0];
        float hd = gb[128];
        gb += 262144;                     // 1024*256
        float z = 1.0f / (1.0f + __expf(-gate));
        float g = (hd >= 0.0f) ? (hd + 0.5f) : 1.0f / (1.0f + __expf(-hd));
        h += z * (g - h);
        *ob = __float2half_rn(h);
        ob += 131072;                     // 1024*128
    }
    dout[16777216 + (size_t)b * 131072 + c * 1024 + px] = h;
}

// ---------------- scan 1: gh px-major -> c-major main out + finals slot 1 --
__global__ void scan1_kernel(float* __restrict__ dout) {
    __shared__ float tr[32][33];
    const int tid = threadIdx.x;
    const int blk = blockIdx.x;           // 512 = b(4) * cblk(4) * pxb(32)
    const int b = blk >> 7, rem = blk & 127;
    const int cblk = rem >> 5, pxb = rem & 31;
    const int c = cblk * 32 + (tid & 31);
    const int pg = tid >> 5;              // 0..7
    const int px0 = pxb * 32 + pg * 4;
    const int c2 = tid >> 3, pq = tid & 7;   // writer role

    float h[4] = {0.5f, 0.5f, 0.5f, 0.5f};
#pragma unroll 1
    for (int s = 0; s < 32; s++) {
        const float* gb = g_gh + ((size_t)(b * 32 + s) * 1024 + px0) * 256 + c;
#pragma unroll
        for (int j = 0; j < 4; j++) {
            float gate = gb[j * 256];
            float hd = gb[j * 256 + 128];
            float z = 1.0f / (1.0f + __expf(-gate));
            float g = (hd >= 0.0f) ? (hd + 0.5f) : 1.0f / (1.0f + __expf(-hd));
            h[j] += z * (g - h[j]);
        }
        __syncthreads();                  // previous iteration's readers done
#pragma unroll
        for (int j = 0; j < 4; j++) tr[pg * 4 + j][tid & 31] = h[j];
        __syncthreads();
        float4 v;
        v.x = tr[pq * 4 + 0][c2];
        v.y = tr[pq * 4 + 1][c2];
        v.z = tr[pq * 4 + 2][c2];
        v.w = tr[pq * 4 + 3][c2];
        *(float4*)(dout + ((size_t)((b * 32 + s) * 128) + cblk * 32 + c2) * 1024 +
                   pxb * 32 + pq * 4) = v;
    }
    float4 f = make_float4(h[0], h[1], h[2], h[3]);
    *(float4*)(dout + 16777216 + 524288 + (size_t)b * 131072 + c * 1024 + px0) = f;
}

// ---------------- launch ----------------
extern "C" void kernel_launch(void* const* d_in, const int* in_sizes, int n_in,
                              void* d_out, int out_size) {
    const float* x  = (const float*)d_in[0];
    const float* w0 = (const float*)d_in[1];
    const float* b0 = (const float*)d_in[2];
    const float* w1 = (const float*)d_in[3];
    const float* b1 = (const float*)d_in[4];
    float* out = (float*)d_out;

    constexpr int SMEM0 = 67584;    // conv0: raw + 2B, epi needs 67584
    constexpr int SMEM1 = 95616;    // conv1: 2 raw + 2B
    cudaFuncSetAttribute(conv_mma_kernel<64, false>,
                         cudaFuncAttributeMaxDynamicSharedMemorySize, SMEM0);
    cudaFuncSetAttribute(conv_mma_kernel<128, true>,
                         cudaFuncAttributeMaxDynamicSharedMemorySize, SMEM1);

    prep_w_kernel<<<1728, 256>>>(w0, w1);
    prep_x_kernel<<<dim3(128, 8), 256>>>(x);
    conv_mma_kernel<64, false><<<dim3(8, 2, 128), 256, SMEM0>>>(b0);
    scan0_kernel<<<2048, 256>>>(out);
    conv_mma_kernel<128, true><<<dim3(8, 2, 128), 256, SMEM1>>>(b1);
    scan1_kernel<<<512, 256>>>(out);
}

// round 14
// speedup vs baseline: 7.5690x; 1.0331x over previous
#include <cuda_runtime.h>
#include <cuda_fp16.h>
#include <cstdint>

// ---------------- scratch (no allocations allowed) ----------------
__device__ __align__(16) __half g_ghh[33554432];    // [bs=128][px=1024][co=256] fp16
__device__ __align__(16) __half g_xh[8388608];      // [bs][px][ci=64] fp16
__device__ __align__(16) __half g_out0h[16777216];  // [bs][px][ci=128] fp16
__device__ __align__(16) __half g_B[442368];        // 27 chunks x [256 co][64 k]
__device__ uint4 g_zero[8] = {};                    // 128 B zeros (halo cp source)

// ---------------- warp MMA helpers (baseline sm_80+ instructions) ----------
__device__ __forceinline__ uint32_t smem_u32(const void* p) {
    uint32_t a;
    asm("{ .reg .u64 t; cvta.to.shared.u64 t, %1; cvt.u32.u64 %0, t; }"
        : "=r"(a) : "l"(p));
    return a;
}
__device__ __forceinline__ void ldmx4(uint32_t* r, uint32_t a) {
    asm volatile("ldmatrix.sync.aligned.m8n8.x4.shared.b16 {%0,%1,%2,%3}, [%4];"
                 : "=r"(r[0]), "=r"(r[1]), "=r"(r[2]), "=r"(r[3]) : "r"(a));
}
__device__ __forceinline__ void mma16816(float* c, const uint32_t* a,
                                         uint32_t b0, uint32_t b1) {
    asm volatile(
        "mma.sync.aligned.m16n8k16.row.col.f32.f16.f16.f32 "
        "{%0,%1,%2,%3}, {%4,%5,%6,%7}, {%8,%9}, {%0,%1,%2,%3};"
        : "+f"(c[0]), "+f"(c[1]), "+f"(c[2]), "+f"(c[3])
        : "r"(a[0]), "r"(a[1]), "r"(a[2]), "r"(a[3]), "r"(b0), "r"(b1));
}
__device__ __forceinline__ void cp16(uint32_t d, const void* s) {
    asm volatile("cp.async.cg.shared.global [%0], [%1], 16;" :: "r"(d), "l"(s));
}
#define CP_COMMIT() asm volatile("cp.async.commit_group;" ::: "memory")
#define CP_WAIT0()  asm volatile("cp.async.wait_group 0;" ::: "memory")

// ---------------- weight prep: fp16 chunks [g][co][kk] ---------------------
__global__ void prep_w_kernel(const float* __restrict__ w0,
                              const float* __restrict__ w1) {
    int e = blockIdx.x * 256 + threadIdx.x;   // grid = 1728 -> 442368 exact
    int g = e >> 14;
    int rem = e & 16383;
    int co = rem >> 6;
    int kk = rem & 63;
    const float* w;
    int CIN, tap, ci;
    if (g < 9) { w = w0; CIN = 64; tap = g; ci = kk; }
    else { int l = g - 9; w = w1; CIN = 128; tap = l % 9; ci = (l / 9) * 64 + kk; }
    g_B[e] = __float2half_rn(w[(co * CIN + ci) * 9 + tap]);
}

// ---------------- x prep: [bs][ci=64][px] fp32 -> [bs][px][ci] fp16 --------
__global__ void prep_x_kernel(const float* __restrict__ x) {
    __shared__ __half sm[128 * 72];   // [p 0..127][ci pad 72]
    const int bs = blockIdx.x, pxb = blockIdx.y;   // grid (128, 8)
    const int tid = threadIdx.x;
    const float* xb = x + (size_t)bs * 65536 + pxb * 128;
#pragma unroll
    for (int k = 0; k < 32; k++) {
        int i = tid + k * 256;        // 8192 = 64 ci * 128 px
        int ci = i >> 7, p = i & 127;
        sm[p * 72 + ci] = __float2half_rn(xb[ci * 1024 + p]);
    }
    __syncthreads();
    uint4* dst = (uint4*)(g_xh + (size_t)bs * 65536 + (size_t)pxb * 128 * 64);
#pragma unroll
    for (int k = 0; k < 4; k++) {
        int i = tid + k * 256;        // 1024 = 128 px * 8 segs
        int p = i >> 3, seg = i & 7;
        dst[p * 8 + seg] = *(uint4*)(sm + p * 72 + seg * 8);
    }
}

// ---------------- smem layout (bytes) ----------------
constexpr int RAW_SZ = 29376;       // 204 rows x 144 B ([y*34+x][ci 64 pad 72])
constexpr int B_SZ = 18432;

// ---------------- conv via warp-level fp16 MMA -----------------------------
// CTA = (4-row px tile, co half, image bs). 256 threads / 8 warps.
// CTA tile: D[128 px][128 co]. Warp tile m32 x n64 (4m x 2n warps).
template <int CIN, bool XG>
__global__ void __launch_bounds__(256, 2)
conv_mma_kernel(const float* __restrict__ bias) {
    extern __shared__ char smem[];
    const uint32_t sb = smem_u32(smem);
    const int tid = threadIdx.x;
    const int wid = tid >> 5;
    const int lane = tid & 31;
    const int h0 = blockIdx.x * 4;     // 4 image rows
    const int coh = blockIdx.y;        // co half 0..1
    const int bs = blockIdx.z;         // 0..127

    const uint32_t SMB0 = (CIN == 64) ? 29376u : 58752u;
    const uint32_t SMB1 = SMB0 + B_SZ;

    const __half* src = XG ? (g_out0h + (size_t)bs * 131072)
                           : (g_xh + (size_t)bs * 65536);
    const int SRC_STRIDE = XG ? 128 : 64;

    // warp tiling: 4 (m) x 2 (n)
    const int m0 = (wid & 3) * 32;
    const int n0r = (wid >> 2) * 64;
    // ldmatrix lane geometry (validated mapping)
    const int mrowA = (lane & 7) + ((lane >> 3) & 1) * 8;
    const int kcolA = (lane >> 4) * 8;
    const int noffB = (lane & 7) + (lane >> 4) * 8;
    const int koffB = ((lane >> 3) & 1) * 8;
    const int px0 = m0 + mrowA, px1 = px0 + 16;
    const uint32_t aB0 = sb +
        (uint32_t)(((px0 >> 5) * 34 + (px0 & 31)) * 144 + kcolA * 2);
    const uint32_t aB1 = sb +
        (uint32_t)(((px1 >> 5) * 34 + (px1 & 31)) * 144 + kcolA * 2);
    const uint32_t bLaneOff = (uint32_t)((n0r + noffB) * 144 + koffB * 2);

    float acc[2][8][4];
#pragma unroll
    for (int m = 0; m < 2; m++)
#pragma unroll
        for (int nb = 0; nb < 8; nb++)
#pragma unroll
            for (int j = 0; j < 4; j++) acc[m][nb][j] = 0.0f;

    const int g_first = (CIN == 64) ? 0 : 9;
    const int g_last  = g_first + 9 * (CIN / 64) - 1;

    auto stage_raw = [&](uint32_t dst, int hh) {
        const __half* s0 = src + hh * 64;
        for (int i = tid; i < 1632; i += 256) {      // 204 rows x 8 segs
            int row = i >> 3, seg = i & 7;
            int y = row / 34, xc = row - y * 34;
            int yy = h0 - 1 + y, xx = xc - 1;
            const void* sp = g_zero;
            if (yy >= 0 && yy < 32 && xx >= 0 && xx < 32)
                sp = s0 + (size_t)(yy * 32 + xx) * SRC_STRIDE + seg * 8;
            cp16(dst + row * 144 + seg * 16, sp);
        }
    };
    auto copy_B = [&](int g, uint32_t dst) {
        const uint4* sB = (const uint4*)(g_B + g * 16384 + coh * 8192);
#pragma unroll
        for (int i = tid; i < 1024; i += 256)
            cp16(dst + (i >> 3) * 144 + (i & 7) * 16, sB + i);
    };

    // ---- prologue: stage raw(cih0) + B(first tap), one group ----
    stage_raw(sb + 0, 0);
    copy_B(g_first, sb + SMB0);
    CP_COMMIT();
    int pb = 0;   // buffer holding the CURRENT tap's B

#pragma unroll 1
    for (int cih = 0; cih < CIN / 64; cih++) {
#pragma unroll 1
        for (int tap = 0; tap < 9; tap++) {
            const int g = g_first + cih * 9 + tap;

            CP_WAIT0();        // current B (and raw groups) complete
            __syncthreads();

            if (XG && g == g_first) {
                stage_raw(sb + RAW_SZ, 1);
                copy_B(g + 1, sb + (pb ? SMB0 : SMB1));
                CP_COMMIT();
            } else if (g < g_last) {
                copy_B(g + 1, sb + (pb ? SMB0 : SMB1));
                CP_COMMIT();
            }

            const uint32_t roff = (uint32_t)(cih * RAW_SZ) +
                (uint32_t)(((tap / 3) * 34 + (tap % 3)) * 144);
            const uint32_t a0 = aB0 + roff, a1 = aB1 + roff;
            const uint32_t bB = sb + (pb ? SMB1 : SMB0) + bLaneOff;

            // ---- 64 MMAs / warp ----
#pragma unroll
            for (int ks = 0; ks < 4; ks++) {
                const uint32_t kb = ks * 32;
                uint32_t Ah0[4], Ah1[4], Bf[4][4];
                ldmx4(Ah0, a0 + kb);
                ldmx4(Ah1, a1 + kb);
#pragma unroll
                for (int p = 0; p < 4; p++) ldmx4(Bf[p], bB + p * 2304 + kb);
#pragma unroll
                for (int p = 0; p < 4; p++) {
                    mma16816(acc[0][2 * p],     Ah0, Bf[p][0], Bf[p][1]);
                    mma16816(acc[1][2 * p],     Ah1, Bf[p][0], Bf[p][1]);
                    mma16816(acc[0][2 * p + 1], Ah0, Bf[p][2], Bf[p][3]);
                    mma16816(acc[1][2 * p + 1], Ah1, Bf[p][2], Bf[p][3]);
                }
            }
            pb ^= 1;
        }
    }

    // ---- epilogue: acc -> epi[px][co] fp32 (pitch 132) -> gh fp16 ----
    __syncthreads();
    float* epi = (float*)smem;
#pragma unroll
    for (int m = 0; m < 2; m++) {
#pragma unroll
        for (int nb = 0; nb < 8; nb++) {
            int px = m0 + m * 16 + (lane >> 2);
            int co = n0r + nb * 8 + 2 * (lane & 3);
            *(float2*)(epi + px * 132 + co) =
                make_float2(acc[m][nb][0], acc[m][nb][1]);
            *(float2*)(epi + (px + 8) * 132 + co) =
                make_float2(acc[m][nb][2], acc[m][nb][3]);
        }
    }
    __syncthreads();
    {
        __half* ghb = g_ghh + ((size_t)bs * 1024 + h0 * 32) * 256 + coh * 128;
        const float4* bv4 = (const float4*)(bias + coh * 128);
        for (int i = tid; i < 2048; i += 256) {
            int px = i >> 4, c8 = i & 15;
            float4 v0 = *(float4*)(epi + px * 132 + c8 * 8);
            float4 v1 = *(float4*)(epi + px * 132 + c8 * 8 + 4);
            float4 b0 = __ldg(bv4 + c8 * 2);
            float4 b1 = __ldg(bv4 + c8 * 2 + 1);
            __half2 h0p = __floats2half2_rn(v0.x + b0.x, v0.y + b0.y);
            __half2 h1p = __floats2half2_rn(v0.z + b0.z, v0.w + b0.w);
            __half2 h2p = __floats2half2_rn(v1.x + b1.x, v1.y + b1.y);
            __half2 h3p = __floats2half2_rn(v1.z + b1.z, v1.w + b1.w);
            uint4 o;
            o.x = *(uint32_t*)&h0p; o.y = *(uint32_t*)&h1p;
            o.z = *(uint32_t*)&h2p; o.w = *(uint32_t*)&h3p;
            *(uint4*)(ghb + (size_t)px * 256 + c8 * 8) = o;
        }
    }
}

// ---------------- scan 0: gh fp16 px-major -> fp16 out0 + finals slot 0 ----
__global__ void scan0_kernel(float* __restrict__ dout) {
    const int tid = threadIdx.x;
    const int blk = blockIdx.x;           // 2048
    const int b = blk >> 9, pxb = blk & 511;
    const int px = pxb * 2 + (tid >> 7);
    const int c = tid & 127;

    const __half* gb = g_ghh + ((size_t)(b * 32) * 1024 + px) * 256 + c;
    __half* ob = g_out0h + ((size_t)(b * 32) * 1024 + px) * 128 + c;

    float h = 0.5f;
#pragma unroll 4
    for (int s = 0; s < 32; s++) {
        float gate = __half2float(gb[0]);
        float hd = __half2float(gb[128]);
        gb += 262144;                     // 1024*256
        float z = 1.0f / (1.0f + __expf(-gate));
        float g = (hd >= 0.0f) ? (hd + 0.5f) : 1.0f / (1.0f + __expf(-hd));
        h += z * (g - h);
        *ob = __float2half_rn(h);
        ob += 131072;                     // 1024*128
    }
    dout[16777216 + (size_t)b * 131072 + c * 1024 + px] = h;
}

// ---------------- scan 1: gh fp16 -> c-major main out + finals slot 1 ------
__global__ void scan1_kernel(float* __restrict__ dout) {
    __shared__ float tr[32][33];
    const int tid = threadIdx.x;
    const int blk = blockIdx.x;           // 512 = b(4) * cblk(4) * pxb(32)
    const int b = blk >> 7, rem = blk & 127;
    const int cblk = rem >> 5, pxb = rem & 31;
    const int c = cblk * 32 + (tid & 31);
    const int pg = tid >> 5;              // 0..7
    const int px0 = pxb * 32 + pg * 4;
    const int c2 = tid >> 3, pq = tid & 7;   // writer role

    float h[4] = {0.5f, 0.5f, 0.5f, 0.5f};
#pragma unroll 1
    for (int s = 0; s < 32; s++) {
        const __half* gb = g_ghh + ((size_t)(b * 32 + s) * 1024 + px0) * 256 + c;
#pragma unroll
        for (int j = 0; j < 4; j++) {
            float gate = __half2float(gb[j * 256]);
            float hd = __half2float(gb[j * 256 + 128]);
            float z = 1.0f / (1.0f + __expf(-gate));
            float g = (hd >= 0.0f) ? (hd + 0.5f) : 1.0f / (1.0f + __expf(-hd));
            h[j] += z * (g - h[j]);
        }
        __syncthreads();                  // previous iteration's readers done
#pragma unroll
        for (int j = 0; j < 4; j++) tr[pg * 4 + j][tid & 31] = h[j];
        __syncthreads();
        float4 v;
        v.x = tr[pq * 4 + 0][c2];
        v.y = tr[pq * 4 + 1][c2];
        v.z = tr[pq * 4 + 2][c2];
        v.w = tr[pq * 4 + 3][c2];
        *(float4*)(dout + ((size_t)((b * 32 + s) * 128) + cblk * 32 + c2) * 1024 +
                   pxb * 32 + pq * 4) = v;
    }
    float4 f = make_float4(h[0], h[1], h[2], h[3]);
    *(float4*)(dout + 16777216 + 524288 + (size_t)b * 131072 + c * 1024 + px0) = f;
}

// ---------------- launch ----------------
extern "C" void kernel_launch(void* const* d_in, const int* in_sizes, int n_in,
                              void* d_out, int out_size) {
    const float* x  = (const float*)d_in[0];
    const float* w0 = (const float*)d_in[1];
    const float* b0 = (const float*)d_in[2];
    const float* w1 = (const float*)d_in[3];
    const float* b1 = (const float*)d_in[4];
    float* out = (float*)d_out;

    constexpr int SMEM0 = 67584;    // conv0: raw + 2B; epi needs 67584
    constexpr int SMEM1 = 95616;    // conv1: 2 raw + 2B
    cudaFuncSetAttribute(conv_mma_kernel<64, false>,
                         cudaFuncAttributeMaxDynamicSharedMemorySize, SMEM0);
    cudaFuncSetAttribute(conv_mma_kernel<128, true>,
                         cudaFuncAttributeMaxDynamicSharedMemorySize, SMEM1);

    prep_w_kernel<<<1728, 256>>>(w0, w1);
    prep_x_kernel<<<dim3(128, 8), 256>>>(x);
    conv_mma_kernel<64, false><<<dim3(8, 2, 128), 256, SMEM0>>>(b0);
    scan0_kernel<<<2048, 256>>>(out);
    conv_mma_kernel<128, true><<<dim3(8, 2, 128), 256, SMEM1>>>(b1);
    scan1_kernel<<<512, 256>>>(out);
}